// round 9
// baseline (speedup 1.0000x reference)
#include <cuda_runtime.h>
#include <cstdint>
#include <math.h>

#define BATCH 2
#define SEQ   2048
#define DMODEL 2048
#define NH    16
#define HD    128
#define CACHEDLEN 2048
#define TTOT  (CACHEDLEN + SEQ)      // 4096

// ---------------- scratch (static device globals) ----------------
__device__ float g_Q [(size_t)BATCH*NH*SEQ*HD];   // [B,H,S,HD] pre-scaled+rounded
__device__ float g_Kn[(size_t)BATCH*NH*SEQ*HD];   // [B,H,S,HD] rounded
__device__ float g_Vn[(size_t)BATCH*NH*SEQ*HD];   // [B,H,S,HD] rounded (intermediate)
__device__ float g_Vt[(size_t)BATCH*NH*HD*TTOT];  // [B,H,HD,T] rounded, transposed V
__device__ float g_At[(size_t)BATCH*SEQ*DMODEL];  // [B,S,D]    rounded
__device__ float g_X [(size_t)BATCH*SEQ*DMODEL];  // rounded hidden states
__device__ float g_Wr[(size_t)4*DMODEL*DMODEL];   // rounded Wq,Wk,Wv,Wo
__device__ float g_Kc[(size_t)BATCH*NH*CACHEDLEN*HD];  // rounded k_cache

// ================= helpers =================
__device__ __forceinline__ uint32_t smem_u32(const void* p) {
    uint32_t a;
    asm("{ .reg .u64 t; cvta.to.shared.u64 t, %1; cvt.u32.u64 %0, t; }" : "=r"(a) : "l"(p));
    return a;
}
__device__ __forceinline__ void cp_async16(uint32_t saddr, const void* gptr) {
    asm volatile("cp.async.cg.shared.global [%0], [%1], 16;\n" :: "r"(saddr), "l"(gptr));
}
#define CP_COMMIT() asm volatile("cp.async.commit_group;\n" ::: "memory")
#define CP_WAIT1()  asm volatile("cp.async.wait_group 1;\n" ::: "memory")

__device__ __forceinline__ uint32_t f2tf32(float f) {
    uint32_t r;
    asm("cvt.rna.tf32.f32 %0, %1;" : "=r"(r) : "f"(f));
    return r;
}
__device__ __forceinline__ float roundtf(float f) { return __uint_as_float(f2tf32(f)); }

__device__ __forceinline__ void mma_tf32(float c[4], const uint32_t a[4], const uint32_t b[2]) {
    asm volatile(
        "mma.sync.aligned.m16n8k8.row.col.f32.tf32.tf32.f32 "
        "{%0,%1,%2,%3}, {%4,%5,%6,%7}, {%8,%9}, {%0,%1,%2,%3};"
        : "+f"(c[0]), "+f"(c[1]), "+f"(c[2]), "+f"(c[3])
        : "r"(a[0]), "r"(a[1]), "r"(a[2]), "r"(a[3]), "r"(b[0]), "r"(b[1]));
}
__device__ __forceinline__ void ldsm_x4(uint32_t r[4], uint32_t saddr) {
    asm volatile("ldmatrix.sync.aligned.m8n8.x4.shared.b16 {%0,%1,%2,%3}, [%4];"
                 : "=r"(r[0]), "=r"(r[1]), "=r"(r[2]), "=r"(r[3]) : "r"(saddr));
}

// ================= tf32 pre-rounding kernel (4-wide) =================
__global__ __launch_bounds__(256) void round_tf32_k(const float4* __restrict__ in,
                                                    float4* __restrict__ out, int n4)
{
    int i = (blockIdx.x * blockDim.x + threadIdx.x) * 4;
    if (i + 3 < n4) {
        float4 a = in[i], b = in[i+1], c = in[i+2], d = in[i+3];
        a.x=roundtf(a.x); a.y=roundtf(a.y); a.z=roundtf(a.z); a.w=roundtf(a.w);
        b.x=roundtf(b.x); b.y=roundtf(b.y); b.z=roundtf(b.z); b.w=roundtf(b.w);
        c.x=roundtf(c.x); c.y=roundtf(c.y); c.z=roundtf(c.z); c.w=roundtf(c.w);
        d.x=roundtf(d.x); d.y=roundtf(d.y); d.z=roundtf(d.z); d.w=roundtf(d.w);
        out[i] = a; out[i+1] = b; out[i+2] = c; out[i+3] = d;
    }
}

// ===== V: round + transpose [bh, srcLen, HD] -> g_Vt[bh, HD, TTOT] at dstOff =====
// Coalesced both sides via 32x33 smem tile. roundtf is idempotent, so this is
// used for raw v_cache (rounds) and for already-rounded V_new (identity).
__global__ __launch_bounds__(256) void vtrans_k(const float* __restrict__ src,
                                                float* __restrict__ vt,
                                                int srcLen, int dstOff)
{
    __shared__ float tile[32][33];
    int bh = blockIdx.z;
    int t0 = blockIdx.x * 32, d0 = blockIdx.y * 32;
    int tx = threadIdx.x & 31, ty = threadIdx.x >> 5;   // ty 0..7
    const float* s = src + ((size_t)bh * srcLen + t0) * HD + d0;
#pragma unroll
    for (int r = 0; r < 4; ++r) {
        int row = ty + r * 8;
        tile[row][tx] = roundtf(s[(size_t)row * HD + tx]);
    }
    __syncthreads();
    float* d = vt + ((size_t)bh * HD + d0) * TTOT + dstOff + t0;
#pragma unroll
    for (int r = 0; r < 4; ++r) {
        int row = ty + r * 8;
        d[(size_t)row * TTOT + tx] = tile[tx][row];
    }
}

// ================= tf32 mma.sync GEMM =================
#define BK       32
#define NCHUNK   (DMODEL / BK)
#define ROWPAD   36
#define TILE_FLOATS (128 * ROWPAD)
#define STAGE_FLOATS (2 * TILE_FLOATS)
#define NSTAGES  3
#define GEMM_SMEM (NSTAGES * STAGE_FLOATS * 4)

__device__ __forceinline__ void load_stage(const float* __restrict__ A,
                                           const float* __restrict__ W,
                                           int m0, int n0, int k0,
                                           uint32_t sa, int tid)
{
#pragma unroll
    for (int i = 0; i < 4; ++i) {
        int c = tid + 256 * i;
        int row = c >> 3;
        int j = c & 7;
        cp_async16(sa + (uint32_t)(row * (ROWPAD * 4) + j * 16),
                   A + (size_t)(m0 + row) * DMODEL + k0 + j * 4);
    }
    uint32_t sb = sa + TILE_FLOATS * 4;
#pragma unroll
    for (int i = 0; i < 4; ++i) {
        int c = tid + 256 * i;
        int row = c >> 3;
        int j = c & 7;
        cp_async16(sb + (uint32_t)(row * (ROWPAD * 4) + j * 16),
                   W + (size_t)(n0 + row) * DMODEL + k0 + j * 4);
    }
}

__device__ __forceinline__ void gemm_body(const float* __restrict__ A,
                                          const float* __restrict__ W,
                                          uint32_t smb, int tid, int m0, int n0,
                                          float acc[4][4][4])
{
    int lane = tid & 31;
    int w = tid >> 5;
    int wm = w >> 2;
    int wn = w & 3;
    int lr16 = lane & 15;
    int lc4  = ((lane >> 4) & 1) * 4;
    int br   = (lane & 7) + ((lane >> 4) & 1) * 8;
    int bc4  = ((lane >> 3) & 1) * 4;
    uint32_t a_off[4], b_off[2];
#pragma unroll
    for (int mi = 0; mi < 4; ++mi)
        a_off[mi] = (uint32_t)(((wm * 64 + mi * 16 + lr16) * ROWPAD + lc4) * 4);
#pragma unroll
    for (int njp = 0; njp < 2; ++njp)
        b_off[njp] = (uint32_t)(((wn * 32 + njp * 16 + br) * ROWPAD + bc4) * 4);

    load_stage(A, W, m0, n0, 0, smb, tid);
    CP_COMMIT();
    load_stage(A, W, m0, n0, BK, smb + STAGE_FLOATS * 4, tid);
    CP_COMMIT();

    for (int it = 0; it < NCHUNK; ++it) {
        uint32_t sA = smb + (uint32_t)((it % NSTAGES) * STAGE_FLOATS * 4);
        uint32_t sB = sA + TILE_FLOATS * 4;
        CP_WAIT1();
        __syncthreads();

#pragma unroll
        for (int s = 0; s < 4; ++s) {
            uint32_t koff = (uint32_t)(s * 32);
            uint32_t af[4][4], bq[2][4];
#pragma unroll
            for (int mi = 0; mi < 4; ++mi) ldsm_x4(af[mi], sA + a_off[mi] + koff);
#pragma unroll
            for (int njp = 0; njp < 2; ++njp) ldsm_x4(bq[njp], sB + b_off[njp] + koff);
#pragma unroll
            for (int mi = 0; mi < 4; ++mi)
#pragma unroll
                for (int nj = 0; nj < 4; ++nj)
                    mma_tf32(acc[mi][nj], af[mi], &bq[nj >> 1][(nj & 1) * 2]);
        }

        if (it + 2 < NCHUNK)
            load_stage(A, W, m0, n0, (it + 2) * BK,
                       smb + (uint32_t)(((it + 2) % NSTAGES) * STAGE_FLOATS * 4), tid);
        CP_COMMIT();
    }
}

// Fused QKV projection: blockIdx.z selects proj (0=Q scaled, 1=K, 2=V).
// All outputs coalesced float2 scatters to [B,H,S,HD].
__global__ __launch_bounds__(256) void gemm_qkv(const float* __restrict__ A,
                                                const float* __restrict__ W0,
                                                float* __restrict__ Qo,
                                                float* __restrict__ Ko,
                                                float* __restrict__ Vo)
{
    extern __shared__ float sm[];
    uint32_t smb = smem_u32(sm);
    int tid = threadIdx.x;
    int pz = blockIdx.z;
    const float* W = W0 + (size_t)pz * DMODEL * DMODEL;
    float* C = (pz == 0) ? Qo : ((pz == 1) ? Ko : Vo);
    float sc = (pz == 0) ? 0.088388347648318447f : 1.0f;
    int m0 = blockIdx.y * 128, n0 = blockIdx.x * 128;

    float acc[4][4][4];
#pragma unroll
    for (int i = 0; i < 4; ++i)
#pragma unroll
        for (int j = 0; j < 4; ++j)
#pragma unroll
            for (int r = 0; r < 4; ++r) acc[i][j][r] = 0.f;

    gemm_body(A, W, smb, tid, m0, n0, acc);

    int lane = tid & 31;
    int w = tid >> 5, wm = w >> 2, wn = w & 3;
    int g = lane >> 2, tg = lane & 3;
#pragma unroll
    for (int mi = 0; mi < 4; ++mi) {
#pragma unroll
        for (int nj = 0; nj < 4; ++nj) {
            int m = m0 + wm * 64 + mi * 16 + g;
            int n = n0 + wn * 32 + nj * 8 + 2 * tg;
            float v0 = roundtf(acc[mi][nj][0] * sc);
            float v1 = roundtf(acc[mi][nj][1] * sc);
            float v2 = roundtf(acc[mi][nj][2] * sc);
            float v3 = roundtf(acc[mi][nj][3] * sc);
            int h_  = n >> 7;
            int hd_ = n & 127;
            {
                int b_ = m >> 11, s_ = m & 2047;
                *reinterpret_cast<float2*>(
                    C + ((((size_t)b_ * NH + h_) * SEQ + s_) * HD + hd_)) = make_float2(v0, v1);
            }
            {
                int m2 = m + 8;
                int b_ = m2 >> 11, s_ = m2 & 2047;
                *reinterpret_cast<float2*>(
                    C + ((((size_t)b_ * NH + h_) * SEQ + s_) * HD + hd_)) = make_float2(v2, v3);
            }
        }
    }
}

// Output projection: plain row-major out.
__global__ __launch_bounds__(256) void gemm_out(const float* __restrict__ A,
                                                const float* __restrict__ W,
                                                float* __restrict__ C)
{
    extern __shared__ float sm[];
    uint32_t smb = smem_u32(sm);
    int tid = threadIdx.x;
    int m0 = blockIdx.y * 128, n0 = blockIdx.x * 128;

    float acc[4][4][4];
#pragma unroll
    for (int i = 0; i < 4; ++i)
#pragma unroll
        for (int j = 0; j < 4; ++j)
#pragma unroll
            for (int r = 0; r < 4; ++r) acc[i][j][r] = 0.f;

    gemm_body(A, W, smb, tid, m0, n0, acc);

    int lane = tid & 31;
    int w = tid >> 5, wm = w >> 2, wn = w & 3;
    int g = lane >> 2, tg = lane & 3;
#pragma unroll
    for (int mi = 0; mi < 4; ++mi) {
#pragma unroll
        for (int nj = 0; nj < 4; ++nj) {
            int m = m0 + wm * 64 + mi * 16 + g;
            int n = n0 + wn * 32 + nj * 8 + 2 * tg;
            *reinterpret_cast<float2*>(C + (size_t)m * DMODEL + n) =
                make_float2(acc[mi][nj][0], acc[mi][nj][1]);
            *reinterpret_cast<float2*>(C + (size_t)(m + 8) * DMODEL + n) =
                make_float2(acc[mi][nj][2], acc[mi][nj][3]);
        }
    }
}

// ================= tensor-core flash attention, 2 CTAs/SM, all-ldmatrix ======
#define KVT   32
#define DPADK 132
#define VTPAD 36
#define QPAD  132
#define PPAD  36
#define AT_K    0
#define AT_V    (2 * KVT * DPADK)                 // 8448
#define AT_QS   (AT_V + 2 * HD * VTPAD)           // 17664
#define AT_PS   (AT_QS + 64 * QPAD)               // 26112
#define AT_LROW (AT_PS + 64 * PPAD)               // 28416
#define ATTN_SMEM ((AT_LROW + 64) * 4)            // 113920 B

__device__ __forceinline__ void load_kv32(const float* __restrict__ kcb,
                                          const float* __restrict__ knb,
                                          const float* __restrict__ vtb,
                                          int t0, int st, uint32_t smb, int tid)
{
    uint32_t sk = smb + (uint32_t)((AT_K + st * KVT * DPADK) * 4);
    uint32_t sv = smb + (uint32_t)((AT_V + st * HD * VTPAD) * 4);
#pragma unroll
    for (int i = 0; i < 4; ++i) {
        int idx = tid + 256 * i;
        int row = idx >> 5;
        int j = idx & 31;
        int t = t0 + row;
        const float* ks = (t < CACHEDLEN) ? kcb + (size_t)t * HD
                                          : knb + (size_t)(t - CACHEDLEN) * HD;
        cp_async16(sk + (uint32_t)(row * (DPADK * 4) + j * 16), ks + j * 4);
    }
#pragma unroll
    for (int i = 0; i < 4; ++i) {
        int idx = tid + 256 * i;
        int row = idx >> 3;               // 0..127 (d)
        int ch = idx & 7;
        cp_async16(sv + (uint32_t)(row * (VTPAD * 4) + ch * 16),
                   vtb + (size_t)row * TTOT + t0 + ch * 4);
    }
}

__global__ __launch_bounds__(256, 2) void attn_tc(
    const float* __restrict__ Q,
    const float* __restrict__ Kn,
    const float* __restrict__ kc,
    const float* __restrict__ vt,
    float* __restrict__ O)
{
    extern __shared__ float sm[];
    uint32_t smb = smem_u32(sm);
    float* Ps   = sm + AT_PS;
    float* lrow = sm + AT_LROW;
    uint32_t qsb = smb + AT_QS * 4;
    uint32_t psb = smb + AT_PS * 4;

    int qt = blockIdx.x, h = blockIdx.y, b = blockIdx.z;
    int tid = threadIdx.x, lane = tid & 31, w = tid >> 5;
    int wm = w >> 1, wn = w & 1;
    int g = lane >> 2, tg = lane & 3;
    int q0 = qt * 64;
    size_t bh = (size_t)b * NH + h;

    if (tid < 64) lrow[tid] = 0.f;

    int lr16 = lane & 15;
    int lc4  = ((lane >> 4) & 1) * 4;
    int br   = (lane & 7) + ((lane >> 4) & 1) * 8;
    int bc4  = ((lane >> 3) & 1) * 4;
    uint32_t a_off = (uint32_t)(((wm * 16 + lr16) * QPAD + lc4) * 4);
    uint32_t k_off = (uint32_t)(((wn * 16 + br) * DPADK + bc4) * 4);
    uint32_t p_off = (uint32_t)(((wm * 16 + lr16) * PPAD + lc4) * 4);
    uint32_t v_off[4];
#pragma unroll
    for (int njp = 0; njp < 4; ++njp)
        v_off[njp] = (uint32_t)(((wn * 64 + njp * 16 + br) * VTPAD + bc4) * 4);

    const float* kcb = kc + bh * CACHEDLEN * HD;
    const float* knb = Kn + bh * SEQ * HD;
    const float* vtb = vt + bh * HD * TTOT;

    const float* Qg = Q + (bh * SEQ + q0) * HD;
#pragma unroll
    for (int i = 0; i < 8; ++i) {
        int idx = tid + 256 * i;
        int row = idx >> 5;
        int j = idx & 31;
        cp_async16(qsb + (uint32_t)(row * (QPAD * 4) + j * 16),
                   Qg + (size_t)row * HD + j * 4);
    }

    float oa[8][4];
#pragma unroll
    for (int j = 0; j < 8; ++j)
#pragma unroll
        for (int r = 0; r < 4; ++r) oa[j][r] = 0.f;

    int nt = (CACHEDLEN + q0 + 64) / KVT;
    load_kv32(kcb, knb, vtb, 0, 0, smb, tid);
    CP_COMMIT();

    for (int it = 0; it < nt; ++it) {
        if (it + 1 < nt)
            load_kv32(kcb, knb, vtb, (it + 1) * KVT, (it + 1) & 1, smb, tid);
        CP_COMMIT();
        CP_WAIT1();
        __syncthreads();

        uint32_t sK = smb + (uint32_t)((AT_K + (it & 1) * KVT * DPADK) * 4);
        uint32_t sV = smb + (uint32_t)((AT_V + (it & 1) * HD * VTPAD) * 4);

        // ---- S = Q K^T ----
        float sc[2][4];
#pragma unroll
        for (int nj = 0; nj < 2; ++nj)
#pragma unroll
            for (int r = 0; r < 4; ++r) sc[nj][r] = 0.f;

#pragma unroll
        for (int s = 0; s < 16; ++s) {
            uint32_t koff = (uint32_t)(s * 32);
            uint32_t af[4], kq[4];
            ldsm_x4(af, qsb + a_off + koff);
            ldsm_x4(kq, sK + k_off + koff);
            mma_tf32(sc[0], af, &kq[0]);
            mma_tf32(sc[1], af, &kq[2]);
        }

        // ---- exp + mask + row sums + store P ----
        int qa0 = CACHEDLEN + q0 + wm * 16 + g;
        int tb  = it * KVT + wn * 16;
        float rs0 = 0.f, rs1 = 0.f;
#pragma unroll
        for (int nj = 0; nj < 2; ++nj) {
            int c0 = tb + nj * 8 + 2 * tg;
            float p00 = (c0     <= qa0    ) ? roundtf(__expf(sc[nj][0])) : 0.f;
            float p01 = (c0 + 1 <= qa0    ) ? roundtf(__expf(sc[nj][1])) : 0.f;
            float p10 = (c0     <= qa0 + 8) ? roundtf(__expf(sc[nj][2])) : 0.f;
            float p11 = (c0 + 1 <= qa0 + 8) ? roundtf(__expf(sc[nj][3])) : 0.f;
            rs0 += p00 + p01;
            rs1 += p10 + p11;
            int pr = wm * 16 + g;
            int pcol = wn * 16 + nj * 8 + 2 * tg;
            *reinterpret_cast<float2*>(&Ps[pr * PPAD + pcol])       = make_float2(p00, p01);
            *reinterpret_cast<float2*>(&Ps[(pr + 8) * PPAD + pcol]) = make_float2(p10, p11);
        }
        rs0 += __shfl_xor_sync(0xffffffffu, rs0, 1);
        rs0 += __shfl_xor_sync(0xffffffffu, rs0, 2);
        rs1 += __shfl_xor_sync(0xffffffffu, rs1, 1);
        rs1 += __shfl_xor_sync(0xffffffffu, rs1, 2);
        if (tg == 0) {
            atomicAdd(&lrow[wm * 16 + g], rs0);
            atomicAdd(&lrow[wm * 16 + g + 8], rs1);
        }
        __syncthreads();

        // ---- O += P V : all fragments via ldmatrix ----
#pragma unroll
        for (int s = 0; s < 4; ++s) {
            uint32_t koff = (uint32_t)(s * 32);
            uint32_t pq[4];
            ldsm_x4(pq, psb + p_off + koff);
            uint32_t vq[4][4];
#pragma unroll
            for (int njp = 0; njp < 4; ++njp)
                ldsm_x4(vq[njp], sV + v_off[njp] + koff);
#pragma unroll
            for (int nj = 0; nj < 8; ++nj)
                mma_tf32(oa[nj], pq, &vq[nj >> 1][(nj & 1) * 2]);
        }
        __syncthreads();
    }

    float inv0 = 1.f / lrow[wm * 16 + g];
    float inv1 = 1.f / lrow[wm * 16 + g + 8];
    int row0 = q0 + wm * 16 + g;
#pragma unroll
    for (int nj = 0; nj < 8; ++nj) {
        int d = wn * 64 + nj * 8 + 2 * tg;
        float* dst0 = O + ((size_t)b * SEQ + row0) * DMODEL + h * HD + d;
        float* dst1 = O + ((size_t)b * SEQ + row0 + 8) * DMODEL + h * HD + d;
        *reinterpret_cast<float2*>(dst0) =
            make_float2(roundtf(oa[nj][0] * inv0), roundtf(oa[nj][1] * inv0));
        *reinterpret_cast<float2*>(dst1) =
            make_float2(roundtf(oa[nj][2] * inv1), roundtf(oa[nj][3] * inv1));
    }
}

// ---------------- launch ----------------
extern "C" void kernel_launch(void* const* d_in, const int* in_sizes, int n_in,
                              void* d_out, int out_size)
{
    const float* X  = (const float*)d_in[0];
    const float* Wq = (const float*)d_in[1];
    const float* Wk = (const float*)d_in[2];
    const float* Wv = (const float*)d_in[3];
    const float* Wo = (const float*)d_in[4];
    const float* kc = (const float*)d_in[5];
    const float* vc = (const float*)d_in[6];

    float *Qp, *Kp, *Vp, *Vtp, *Ap, *Xp, *Wp, *Kcp;
    cudaGetSymbolAddress((void**)&Qp,  g_Q);
    cudaGetSymbolAddress((void**)&Kp,  g_Kn);
    cudaGetSymbolAddress((void**)&Vp,  g_Vn);
    cudaGetSymbolAddress((void**)&Vtp, g_Vt);
    cudaGetSymbolAddress((void**)&Ap,  g_At);
    cudaGetSymbolAddress((void**)&Xp,  g_X);
    cudaGetSymbolAddress((void**)&Wp,  g_Wr);
    cudaGetSymbolAddress((void**)&Kcp, g_Kc);

    cudaFuncSetAttribute(gemm_qkv, cudaFuncAttributeMaxDynamicSharedMemorySize, GEMM_SMEM);
    cudaFuncSetAttribute(gemm_out, cudaFuncAttributeMaxDynamicSharedMemorySize, GEMM_SMEM);
    cudaFuncSetAttribute(attn_tc,  cudaFuncAttributeMaxDynamicSharedMemorySize, ATTN_SMEM);

    const int NX = BATCH * SEQ * DMODEL / 4;
    const int NW = DMODEL * DMODEL / 4;
    const int NC = BATCH * NH * CACHEDLEN * HD / 4;

    round_tf32_k<<<NX / 1024, 256>>>((const float4*)X,  (float4*)Xp,  NX);
    round_tf32_k<<<NW / 1024, 256>>>((const float4*)Wq, (float4*)(Wp + 0L * DMODEL * DMODEL), NW);
    round_tf32_k<<<NW / 1024, 256>>>((const float4*)Wk, (float4*)(Wp + 1L * DMODEL * DMODEL), NW);
    round_tf32_k<<<NW / 1024, 256>>>((const float4*)Wv, (float4*)(Wp + 2L * DMODEL * DMODEL), NW);
    round_tf32_k<<<NW / 1024, 256>>>((const float4*)Wo, (float4*)(Wp + 3L * DMODEL * DMODEL), NW);
    round_tf32_k<<<NC / 1024, 256>>>((const float4*)kc, (float4*)Kcp, NC);
    // v_cache: round + transpose into Vt columns [0, CACHEDLEN)
    vtrans_k<<<dim3(CACHEDLEN / 32, HD / 32, BATCH * NH), 256>>>(vc, Vtp, CACHEDLEN, 0);

    dim3 gq(DMODEL / 128, (BATCH * SEQ) / 128, 3);   // fused QKV
    gemm_qkv<<<gq, 256, GEMM_SMEM>>>(Xp, Wp, Qp, Kp, Vp);

    // V_new: transpose into Vt columns [CACHEDLEN, TTOT)  (roundtf idempotent)
    vtrans_k<<<dim3(SEQ / 32, HD / 32, BATCH * NH), 256>>>(Vp, Vtp, SEQ, CACHEDLEN);

    attn_tc<<<dim3(SEQ / 64, NH, BATCH), 256, ATTN_SMEM>>>(Qp, Kp, Kcp, Vtp, Ap);

    dim3 gg(DMODEL / 128, (BATCH * SEQ) / 128);
    gemm_out<<<gg, 256, GEMM_SMEM>>>(Ap, Wp + 3L * DMODEL * DMODEL, (float*)d_out);
}

// round 10
// speedup vs baseline: 1.0782x; 1.0782x over previous
#include <cuda_runtime.h>
#include <cstdint>
#include <math.h>

#define BATCH 2
#define SEQ   2048
#define DMODEL 2048
#define NH    16
#define HD    128
#define CACHEDLEN 2048

// ---------------- scratch (static device globals) ----------------
__device__ float g_Q [(size_t)BATCH*NH*SEQ*HD];   // [B,H,S,HD] pre-scaled+rounded
__device__ float g_Kn[(size_t)BATCH*NH*SEQ*HD];   // [B,H,S,HD] rounded
__device__ float g_Vn[(size_t)BATCH*NH*SEQ*HD];   // [B,H,S,HD] rounded
__device__ float g_At[(size_t)BATCH*SEQ*DMODEL];  // [B,S,D]    rounded
__device__ float g_X [(size_t)BATCH*SEQ*DMODEL];  // rounded hidden states
__device__ float g_Wr[(size_t)4*DMODEL*DMODEL];   // rounded Wq,Wk,Wv,Wo
__device__ float g_Kc[(size_t)BATCH*NH*CACHEDLEN*HD];  // rounded k_cache
__device__ float g_Vc[(size_t)BATCH*NH*CACHEDLEN*HD];  // rounded v_cache

// ================= helpers =================
__device__ __forceinline__ uint32_t smem_u32(const void* p) {
    uint32_t a;
    asm("{ .reg .u64 t; cvta.to.shared.u64 t, %1; cvt.u32.u64 %0, t; }" : "=r"(a) : "l"(p));
    return a;
}
__device__ __forceinline__ void cp_async16(uint32_t saddr, const void* gptr) {
    asm volatile("cp.async.cg.shared.global [%0], [%1], 16;\n" :: "r"(saddr), "l"(gptr));
}
#define CP_COMMIT() asm volatile("cp.async.commit_group;\n" ::: "memory")
#define CP_WAIT1()  asm volatile("cp.async.wait_group 1;\n" ::: "memory")

__device__ __forceinline__ uint32_t f2tf32(float f) {
    uint32_t r;
    asm("cvt.rna.tf32.f32 %0, %1;" : "=r"(r) : "f"(f));
    return r;
}
__device__ __forceinline__ float roundtf(float f) { return __uint_as_float(f2tf32(f)); }

__device__ __forceinline__ void mma_tf32(float c[4], const uint32_t a[4], const uint32_t b[2]) {
    asm volatile(
        "mma.sync.aligned.m16n8k8.row.col.f32.tf32.tf32.f32 "
        "{%0,%1,%2,%3}, {%4,%5,%6,%7}, {%8,%9}, {%0,%1,%2,%3};"
        : "+f"(c[0]), "+f"(c[1]), "+f"(c[2]), "+f"(c[3])
        : "r"(a[0]), "r"(a[1]), "r"(a[2]), "r"(a[3]), "r"(b[0]), "r"(b[1]));
}
__device__ __forceinline__ void ldsm_x4(uint32_t r[4], uint32_t saddr) {
    asm volatile("ldmatrix.sync.aligned.m8n8.x4.shared.b16 {%0,%1,%2,%3}, [%4];"
                 : "=r"(r[0]), "=r"(r[1]), "=r"(r[2]), "=r"(r[3]) : "r"(saddr));
}

// ================= tf32 pre-rounding kernels =================
__global__ __launch_bounds__(256) void round_tf32_k(const float4* __restrict__ in,
                                                    float4* __restrict__ out, int n4)
{
    int i = (blockIdx.x * blockDim.x + threadIdx.x) * 4;
    if (i + 3 < n4) {
        float4 a = in[i], b = in[i+1], c = in[i+2], d = in[i+3];
        a.x=roundtf(a.x); a.y=roundtf(a.y); a.z=roundtf(a.z); a.w=roundtf(a.w);
        b.x=roundtf(b.x); b.y=roundtf(b.y); b.z=roundtf(b.z); b.w=roundtf(b.w);
        c.x=roundtf(c.x); c.y=roundtf(c.y); c.z=roundtf(c.z); c.w=roundtf(c.w);
        d.x=roundtf(d.x); d.y=roundtf(d.y); d.z=roundtf(d.z); d.w=roundtf(d.w);
        out[i] = a; out[i+1] = b; out[i+2] = c; out[i+3] = d;
    }
}

// All four weight matrices in one launch: blockIdx.y selects the source.
__global__ __launch_bounds__(256) void round_w4_k(const float4* __restrict__ w0,
                                                  const float4* __restrict__ w1,
                                                  const float4* __restrict__ w2,
                                                  const float4* __restrict__ w3,
                                                  float4* __restrict__ out, int n4)
{
    const float4* src = (blockIdx.y == 0) ? w0 : (blockIdx.y == 1) ? w1
                      : (blockIdx.y == 2) ? w2 : w3;
    float4* dst = out + (size_t)blockIdx.y * n4;
    int i = (blockIdx.x * blockDim.x + threadIdx.x) * 4;
    if (i + 3 < n4) {
        float4 a = src[i], b = src[i+1], c = src[i+2], d = src[i+3];
        a.x=roundtf(a.x); a.y=roundtf(a.y); a.z=roundtf(a.z); a.w=roundtf(a.w);
        b.x=roundtf(b.x); b.y=roundtf(b.y); b.z=roundtf(b.z); b.w=roundtf(b.w);
        c.x=roundtf(c.x); c.y=roundtf(c.y); c.z=roundtf(c.z); c.w=roundtf(c.w);
        d.x=roundtf(d.x); d.y=roundtf(d.y); d.z=roundtf(d.z); d.w=roundtf(d.w);
        dst[i] = a; dst[i+1] = b; dst[i+2] = c; dst[i+3] = d;
    }
}

// ================= tf32 mma.sync GEMM (2 CTAs/SM) =================
#define BK       32
#define NCHUNK   (DMODEL / BK)
#define ROWPAD   36
#define TILE_FLOATS (128 * ROWPAD)
#define STAGE_FLOATS (2 * TILE_FLOATS)
#define NSTAGES  3
#define GEMM_SMEM (NSTAGES * STAGE_FLOATS * 4)    // 110592 B; 2x = 216 KB <= 228 KB/SM

__device__ __forceinline__ void load_stage(const float* __restrict__ A,
                                           const float* __restrict__ W,
                                           int m0, int n0, int k0,
                                           uint32_t sa, int tid)
{
#pragma unroll
    for (int i = 0; i < 4; ++i) {
        int c = tid + 256 * i;
        int row = c >> 3;
        int j = c & 7;
        cp_async16(sa + (uint32_t)(row * (ROWPAD * 4) + j * 16),
                   A + (size_t)(m0 + row) * DMODEL + k0 + j * 4);
    }
    uint32_t sb = sa + TILE_FLOATS * 4;
#pragma unroll
    for (int i = 0; i < 4; ++i) {
        int c = tid + 256 * i;
        int row = c >> 3;
        int j = c & 7;
        cp_async16(sb + (uint32_t)(row * (ROWPAD * 4) + j * 16),
                   W + (size_t)(n0 + row) * DMODEL + k0 + j * 4);
    }
}

__device__ __forceinline__ void gemm_body(const float* __restrict__ A,
                                          const float* __restrict__ W,
                                          uint32_t smb, int tid, int m0, int n0,
                                          float acc[4][4][4])
{
    int lane = tid & 31;
    int w = tid >> 5;
    int wm = w >> 2;
    int wn = w & 3;
    int lr16 = lane & 15;
    int lc4  = ((lane >> 4) & 1) * 4;
    int br   = (lane & 7) + ((lane >> 4) & 1) * 8;
    int bc4  = ((lane >> 3) & 1) * 4;
    uint32_t a_off[4], b_off[2];
#pragma unroll
    for (int mi = 0; mi < 4; ++mi)
        a_off[mi] = (uint32_t)(((wm * 64 + mi * 16 + lr16) * ROWPAD + lc4) * 4);
#pragma unroll
    for (int njp = 0; njp < 2; ++njp)
        b_off[njp] = (uint32_t)(((wn * 32 + njp * 16 + br) * ROWPAD + bc4) * 4);

    load_stage(A, W, m0, n0, 0, smb, tid);
    CP_COMMIT();
    load_stage(A, W, m0, n0, BK, smb + STAGE_FLOATS * 4, tid);
    CP_COMMIT();

    for (int it = 0; it < NCHUNK; ++it) {
        uint32_t sA = smb + (uint32_t)((it % NSTAGES) * STAGE_FLOATS * 4);
        uint32_t sB = sA + TILE_FLOATS * 4;
        CP_WAIT1();
        __syncthreads();

#pragma unroll
        for (int s = 0; s < 4; ++s) {
            uint32_t koff = (uint32_t)(s * 32);
            uint32_t af[4][4], bq[2][4];
#pragma unroll
            for (int mi = 0; mi < 4; ++mi) ldsm_x4(af[mi], sA + a_off[mi] + koff);
#pragma unroll
            for (int njp = 0; njp < 2; ++njp) ldsm_x4(bq[njp], sB + b_off[njp] + koff);
#pragma unroll
            for (int mi = 0; mi < 4; ++mi)
#pragma unroll
                for (int nj = 0; nj < 4; ++nj)
                    mma_tf32(acc[mi][nj], af[mi], &bq[nj >> 1][(nj & 1) * 2]);
        }

        if (it + 2 < NCHUNK)
            load_stage(A, W, m0, n0, (it + 2) * BK,
                       smb + (uint32_t)(((it + 2) % NSTAGES) * STAGE_FLOATS * 4), tid);
        CP_COMMIT();
    }
}

// Fused QKV projection: blockIdx.z selects proj (0=Q scaled, 1=K, 2=V).
__global__ __launch_bounds__(256, 2) void gemm_qkv(const float* __restrict__ A,
                                                   const float* __restrict__ W0,
                                                   float* __restrict__ Qo,
                                                   float* __restrict__ Ko,
                                                   float* __restrict__ Vo)
{
    extern __shared__ float sm[];
    uint32_t smb = smem_u32(sm);
    int tid = threadIdx.x;
    int pz = blockIdx.z;
    const float* W = W0 + (size_t)pz * DMODEL * DMODEL;
    float* C = (pz == 0) ? Qo : ((pz == 1) ? Ko : Vo);
    float sc = (pz == 0) ? 0.088388347648318447f : 1.0f;
    int m0 = blockIdx.y * 128, n0 = blockIdx.x * 128;

    float acc[4][4][4];
#pragma unroll
    for (int i = 0; i < 4; ++i)
#pragma unroll
        for (int j = 0; j < 4; ++j)
#pragma unroll
            for (int r = 0; r < 4; ++r) acc[i][j][r] = 0.f;

    gemm_body(A, W, smb, tid, m0, n0, acc);

    int lane = tid & 31;
    int w = tid >> 5, wm = w >> 2, wn = w & 3;
    int g = lane >> 2, tg = lane & 3;
#pragma unroll
    for (int mi = 0; mi < 4; ++mi) {
#pragma unroll
        for (int nj = 0; nj < 4; ++nj) {
            int m = m0 + wm * 64 + mi * 16 + g;
            int n = n0 + wn * 32 + nj * 8 + 2 * tg;
            float v0 = roundtf(acc[mi][nj][0] * sc);
            float v1 = roundtf(acc[mi][nj][1] * sc);
            float v2 = roundtf(acc[mi][nj][2] * sc);
            float v3 = roundtf(acc[mi][nj][3] * sc);
            int h_  = n >> 7;
            int hd_ = n & 127;
            {
                int b_ = m >> 11, s_ = m & 2047;
                *reinterpret_cast<float2*>(
                    C + ((((size_t)b_ * NH + h_) * SEQ + s_) * HD + hd_)) = make_float2(v0, v1);
            }
            {
                int m2 = m + 8;
                int b_ = m2 >> 11, s_ = m2 & 2047;
                *reinterpret_cast<float2*>(
                    C + ((((size_t)b_ * NH + h_) * SEQ + s_) * HD + hd_)) = make_float2(v2, v3);
            }
        }
    }
}

// Output projection: plain row-major out.
__global__ __launch_bounds__(256, 2) void gemm_out(const float* __restrict__ A,
                                                   const float* __restrict__ W,
                                                   float* __restrict__ C)
{
    extern __shared__ float sm[];
    uint32_t smb = smem_u32(sm);
    int tid = threadIdx.x;
    int m0 = blockIdx.y * 128, n0 = blockIdx.x * 128;

    float acc[4][4][4];
#pragma unroll
    for (int i = 0; i < 4; ++i)
#pragma unroll
        for (int j = 0; j < 4; ++j)
#pragma unroll
            for (int r = 0; r < 4; ++r) acc[i][j][r] = 0.f;

    gemm_body(A, W, smb, tid, m0, n0, acc);

    int lane = tid & 31;
    int w = tid >> 5, wm = w >> 2, wn = w & 3;
    int g = lane >> 2, tg = lane & 3;
#pragma unroll
    for (int mi = 0; mi < 4; ++mi) {
#pragma unroll
        for (int nj = 0; nj < 4; ++nj) {
            int m = m0 + wm * 64 + mi * 16 + g;
            int n = n0 + wn * 32 + nj * 8 + 2 * tg;
            *reinterpret_cast<float2*>(C + (size_t)m * DMODEL + n) =
                make_float2(acc[mi][nj][0], acc[mi][nj][1]);
            *reinterpret_cast<float2*>(C + (size_t)(m + 8) * DMODEL + n) =
                make_float2(acc[mi][nj][2], acc[mi][nj][3]);
        }
    }
}

// ========== tensor-core flash attention (R7: 2 CTAs/SM, KVT=32) ==========
#define KVT   32
#define DPADK 132
#define VPADV 136
#define QPAD  132
#define PPAD  36
#define AT_K    0
#define AT_V    (2 * KVT * DPADK)            // 8448
#define AT_QS   (AT_V + 2 * KVT * VPADV)     // 17152
#define AT_PS   (AT_QS + 64 * QPAD)          // 25600
#define AT_LROW (AT_PS + 64 * PPAD)          // 27904
#define ATTN_SMEM ((AT_LROW + 64) * 4)       // 111872 B

__device__ __forceinline__ void load_kv32(const float* __restrict__ kcb,
                                          const float* __restrict__ vcb,
                                          const float* __restrict__ knb,
                                          const float* __restrict__ vnb,
                                          int t0, int st, uint32_t smb, int tid)
{
    uint32_t sk = smb + (uint32_t)((AT_K + st * KVT * DPADK) * 4);
    uint32_t sv = smb + (uint32_t)((AT_V + st * KVT * VPADV) * 4);
#pragma unroll
    for (int i = 0; i < 4; ++i) {
        int idx = tid + 256 * i;          // 0..1023
        int row = idx >> 5;               // 0..31
        int j = idx & 31;
        int t = t0 + row;
        const float *ks, *vs;
        if (t < CACHEDLEN) { ks = kcb + (size_t)t * HD; vs = vcb + (size_t)t * HD; }
        else               { ks = knb + (size_t)(t - CACHEDLEN) * HD;
                             vs = vnb + (size_t)(t - CACHEDLEN) * HD; }
        cp_async16(sk + (uint32_t)(row * (DPADK * 4) + j * 16), ks + j * 4);
        cp_async16(sv + (uint32_t)(row * (VPADV * 4) + j * 16), vs + j * 4);
    }
}

__global__ __launch_bounds__(256, 2) void attn_tc(
    const float* __restrict__ Q,
    const float* __restrict__ Kn,
    const float* __restrict__ Vn,
    const float* __restrict__ kc,
    const float* __restrict__ vc,
    float* __restrict__ O)
{
    extern __shared__ float sm[];
    uint32_t smb = smem_u32(sm);
    float* Ps   = sm + AT_PS;
    float* lrow = sm + AT_LROW;
    uint32_t qsb = smb + AT_QS * 4;
    uint32_t psb = smb + AT_PS * 4;

    int qt = blockIdx.x, h = blockIdx.y, b = blockIdx.z;
    int tid = threadIdx.x, lane = tid & 31, w = tid >> 5;
    int wm = w >> 1, wn = w & 1;
    int g = lane >> 2, tg = lane & 3;
    int q0 = qt * 64;
    size_t bh = (size_t)b * NH + h;

    if (tid < 64) lrow[tid] = 0.f;

    int lr16 = lane & 15;
    int lc4  = ((lane >> 4) & 1) * 4;
    int br   = (lane & 7) + ((lane >> 4) & 1) * 8;
    int bc4  = ((lane >> 3) & 1) * 4;
    uint32_t a_off = (uint32_t)(((wm * 16 + lr16) * QPAD + lc4) * 4);
    uint32_t k_off = (uint32_t)(((wn * 16 + br) * DPADK + bc4) * 4);
    uint32_t p_off = (uint32_t)(((wm * 16 + lr16) * PPAD + lc4) * 4);

    const float* kcb = kc + bh * CACHEDLEN * HD;
    const float* vcb = vc + bh * CACHEDLEN * HD;
    const float* knb = Kn + bh * SEQ * HD;
    const float* vnb = Vn + bh * SEQ * HD;

    const float* Qg = Q + (bh * SEQ + q0) * HD;
#pragma unroll
    for (int i = 0; i < 8; ++i) {
        int idx = tid + 256 * i;
        int row = idx >> 5;
        int j = idx & 31;
        cp_async16(qsb + (uint32_t)(row * (QPAD * 4) + j * 16),
                   Qg + (size_t)row * HD + j * 4);
    }

    float oa[8][4];
#pragma unroll
    for (int j = 0; j < 8; ++j)
#pragma unroll
        for (int r = 0; r < 4; ++r) oa[j][r] = 0.f;

    int nt = (CACHEDLEN + q0 + 64) / KVT;
    load_kv32(kcb, vcb, knb, vnb, 0, 0, smb, tid);
    CP_COMMIT();

    for (int it = 0; it < nt; ++it) {
        if (it + 1 < nt)
            load_kv32(kcb, vcb, knb, vnb, (it + 1) * KVT, (it + 1) & 1, smb, tid);
        CP_COMMIT();
        CP_WAIT1();
        __syncthreads();

        uint32_t sK = smb + (uint32_t)((AT_K + (it & 1) * KVT * DPADK) * 4);
        const float* Vs = sm + AT_V + (it & 1) * KVT * VPADV;

        // ---- S = Q K^T : warp tile 16x16 ----
        float sc[2][4];
#pragma unroll
        for (int nj = 0; nj < 2; ++nj)
#pragma unroll
            for (int r = 0; r < 4; ++r) sc[nj][r] = 0.f;

#pragma unroll
        for (int s = 0; s < 16; ++s) {
            uint32_t koff = (uint32_t)(s * 32);
            uint32_t af[4], kq[4];
            ldsm_x4(af, qsb + a_off + koff);
            ldsm_x4(kq, sK + k_off + koff);
            mma_tf32(sc[0], af, &kq[0]);
            mma_tf32(sc[1], af, &kq[2]);
        }

        // ---- exp + mask + row sums + store P (tf32-rounded) ----
        int qa0 = CACHEDLEN + q0 + wm * 16 + g;
        int tb  = it * KVT + wn * 16;
        float rs0 = 0.f, rs1 = 0.f;
#pragma unroll
        for (int nj = 0; nj < 2; ++nj) {
            int c0 = tb + nj * 8 + 2 * tg;
            float p00 = (c0     <= qa0    ) ? roundtf(__expf(sc[nj][0])) : 0.f;
            float p01 = (c0 + 1 <= qa0    ) ? roundtf(__expf(sc[nj][1])) : 0.f;
            float p10 = (c0     <= qa0 + 8) ? roundtf(__expf(sc[nj][2])) : 0.f;
            float p11 = (c0 + 1 <= qa0 + 8) ? roundtf(__expf(sc[nj][3])) : 0.f;
            rs0 += p00 + p01;
            rs1 += p10 + p11;
            int pr = wm * 16 + g;
            int pcol = wn * 16 + nj * 8 + 2 * tg;
            *reinterpret_cast<float2*>(&Ps[pr * PPAD + pcol])       = make_float2(p00, p01);
            *reinterpret_cast<float2*>(&Ps[(pr + 8) * PPAD + pcol]) = make_float2(p10, p11);
        }
        rs0 += __shfl_xor_sync(0xffffffffu, rs0, 1);
        rs0 += __shfl_xor_sync(0xffffffffu, rs0, 2);
        rs1 += __shfl_xor_sync(0xffffffffu, rs1, 1);
        rs1 += __shfl_xor_sync(0xffffffffu, rs1, 2);
        if (tg == 0) {
            atomicAdd(&lrow[wm * 16 + g], rs0);
            atomicAdd(&lrow[wm * 16 + g + 8], rs1);
        }
        __syncthreads();

        // ---- O += P V : P frags via ldmatrix, V scalar (conflict-free) ----
#pragma unroll
        for (int s = 0; s < 4; ++s) {
            uint32_t pq[4];
            ldsm_x4(pq, psb + p_off + (uint32_t)(s * 32));
            const float* vrow0 = Vs + (8 * s + tg) * VPADV;
            const float* vrow1 = vrow0 + 4 * VPADV;
#pragma unroll
            for (int nj = 0; nj < 8; ++nj) {
                int d0 = wn * 64 + nj * 8 + g;
                uint32_t bf[2];
                bf[0] = __float_as_uint(vrow0[d0]);
                bf[1] = __float_as_uint(vrow1[d0]);
                mma_tf32(oa[nj], pq, bf);
            }
        }
        __syncthreads();
    }

    float inv0 = 1.f / lrow[wm * 16 + g];
    float inv1 = 1.f / lrow[wm * 16 + g + 8];
    int row0 = q0 + wm * 16 + g;
#pragma unroll
    for (int nj = 0; nj < 8; ++nj) {
        int d = wn * 64 + nj * 8 + 2 * tg;
        float* dst0 = O + ((size_t)b * SEQ + row0) * DMODEL + h * HD + d;
        float* dst1 = O + ((size_t)b * SEQ + row0 + 8) * DMODEL + h * HD + d;
        *reinterpret_cast<float2*>(dst0) =
            make_float2(roundtf(oa[nj][0] * inv0), roundtf(oa[nj][1] * inv0));
        *reinterpret_cast<float2*>(dst1) =
            make_float2(roundtf(oa[nj][2] * inv1), roundtf(oa[nj][3] * inv1));
    }
}

// ---------------- launch ----------------
extern "C" void kernel_launch(void* const* d_in, const int* in_sizes, int n_in,
                              void* d_out, int out_size)
{
    const float* X  = (const float*)d_in[0];
    const float* Wq = (const float*)d_in[1];
    const float* Wk = (const float*)d_in[2];
    const float* Wv = (const float*)d_in[3];
    const float* Wo = (const float*)d_in[4];
    const float* kc = (const float*)d_in[5];
    const float* vc = (const float*)d_in[6];

    float *Qp, *Kp, *Vp, *Ap, *Xp, *Wp, *Kcp, *Vcp;
    cudaGetSymbolAddress((void**)&Qp,  g_Q);
    cudaGetSymbolAddress((void**)&Kp,  g_Kn);
    cudaGetSymbolAddress((void**)&Vp,  g_Vn);
    cudaGetSymbolAddress((void**)&Ap,  g_At);
    cudaGetSymbolAddress((void**)&Xp,  g_X);
    cudaGetSymbolAddress((void**)&Wp,  g_Wr);
    cudaGetSymbolAddress((void**)&Kcp, g_Kc);
    cudaGetSymbolAddress((void**)&Vcp, g_Vc);

    cudaFuncSetAttribute(gemm_qkv, cudaFuncAttributeMaxDynamicSharedMemorySize, GEMM_SMEM);
    cudaFuncSetAttribute(gemm_out, cudaFuncAttributeMaxDynamicSharedMemorySize, GEMM_SMEM);
    cudaFuncSetAttribute(attn_tc,  cudaFuncAttributeMaxDynamicSharedMemorySize, ATTN_SMEM);

    const int NX = BATCH * SEQ * DMODEL / 4;
    const int NW = DMODEL * DMODEL / 4;
    const int NC = BATCH * NH * CACHEDLEN * HD / 4;

    round_tf32_k<<<NX / 1024, 256>>>((const float4*)X,  (float4*)Xp,  NX);
    round_w4_k<<<dim3(NW / 1024, 4), 256>>>((const float4*)Wq, (const float4*)Wk,
                                            (const float4*)Wv, (const float4*)Wo,
                                            (float4*)Wp, NW);
    round_tf32_k<<<NC / 1024, 256>>>((const float4*)kc, (float4*)Kcp, NC);
    round_tf32_k<<<NC / 1024, 256>>>((const float4*)vc, (float4*)Vcp, NC);

    dim3 gq(DMODEL / 128, (BATCH * SEQ) / 128, 3);   // fused QKV
    gemm_qkv<<<gq, 256, GEMM_SMEM>>>(Xp, Wp, Qp, Kp, Vp);

    attn_tc<<<dim3(SEQ / 64, NH, BATCH), 256, ATTN_SMEM>>>(Qp, Kp, Vp, Kcp, Vcp, Ap);

    dim3 gg(DMODEL / 128, (BATCH * SEQ) / 128);
    gemm_out<<<gg, 256, GEMM_SMEM>>>(Ap, Wp + 3L * DMODEL * DMODEL, (float*)d_out);
}

// round 12
// speedup vs baseline: 1.1421x; 1.0593x over previous
#include <cuda_runtime.h>
#include <cstdint>
#include <math.h>

#define BATCH 2
#define SEQ   2048
#define DMODEL 2048
#define NH    16
#define HD    128
#define CACHEDLEN 2048

// ---------------- scratch (static device globals) ----------------
__device__ float g_Q [(size_t)BATCH*NH*SEQ*HD];   // [B,H,S,HD] pre-scaled+rounded
__device__ float g_Kn[(size_t)BATCH*NH*SEQ*HD];   // [B,H,S,HD] rounded
__device__ float g_Vn[(size_t)BATCH*NH*SEQ*HD];   // [B,H,S,HD] rounded
__device__ float g_At[(size_t)BATCH*SEQ*DMODEL];  // [B,S,D]    rounded
__device__ float g_X [(size_t)BATCH*SEQ*DMODEL];  // rounded hidden states
__device__ float g_Wr[(size_t)4*DMODEL*DMODEL];   // rounded Wq,Wk,Wv,Wo
__device__ float g_Kc[(size_t)BATCH*NH*CACHEDLEN*HD];  // rounded k_cache
__device__ float g_Vc[(size_t)BATCH*NH*CACHEDLEN*HD];  // rounded v_cache

// ================= helpers =================
__device__ __forceinline__ uint32_t smem_u32(const void* p) {
    uint32_t a;
    asm("{ .reg .u64 t; cvta.to.shared.u64 t, %1; cvt.u32.u64 %0, t; }" : "=r"(a) : "l"(p));
    return a;
}
__device__ __forceinline__ void cp_async16(uint32_t saddr, const void* gptr) {
    asm volatile("cp.async.cg.shared.global [%0], [%1], 16;\n" :: "r"(saddr), "l"(gptr));
}
#define CP_COMMIT() asm volatile("cp.async.commit_group;\n" ::: "memory")
#define CP_WAIT1()  asm volatile("cp.async.wait_group 1;\n" ::: "memory")
#define CP_WAIT0()  asm volatile("cp.async.wait_group 0;\n" ::: "memory")

__device__ __forceinline__ uint32_t f2tf32(float f) {
    uint32_t r;
    asm("cvt.rna.tf32.f32 %0, %1;" : "=r"(r) : "f"(f));
    return r;
}
__device__ __forceinline__ float roundtf(float f) { return __uint_as_float(f2tf32(f)); }

__device__ __forceinline__ void mma_tf32(float c[4], const uint32_t a[4], const uint32_t b[2]) {
    asm volatile(
        "mma.sync.aligned.m16n8k8.row.col.f32.tf32.tf32.f32 "
        "{%0,%1,%2,%3}, {%4,%5,%6,%7}, {%8,%9}, {%0,%1,%2,%3};"
        : "+f"(c[0]), "+f"(c[1]), "+f"(c[2]), "+f"(c[3])
        : "r"(a[0]), "r"(a[1]), "r"(a[2]), "r"(a[3]), "r"(b[0]), "r"(b[1]));
}
__device__ __forceinline__ void ldsm_x4(uint32_t r[4], uint32_t saddr) {
    asm volatile("ldmatrix.sync.aligned.m8n8.x4.shared.b16 {%0,%1,%2,%3}, [%4];"
                 : "=r"(r[0]), "=r"(r[1]), "=r"(r[2]), "=r"(r[3]) : "r"(saddr));
}

// ================= tf32 pre-rounding kernels =================
__global__ __launch_bounds__(256) void round_tf32_k(const float4* __restrict__ in,
                                                    float4* __restrict__ out, int n4)
{
    int i = (blockIdx.x * blockDim.x + threadIdx.x) * 4;
    if (i + 3 < n4) {
        float4 a = in[i], b = in[i+1], c = in[i+2], d = in[i+3];
        a.x=roundtf(a.x); a.y=roundtf(a.y); a.z=roundtf(a.z); a.w=roundtf(a.w);
        b.x=roundtf(b.x); b.y=roundtf(b.y); b.z=roundtf(b.z); b.w=roundtf(b.w);
        c.x=roundtf(c.x); c.y=roundtf(c.y); c.z=roundtf(c.z); c.w=roundtf(c.w);
        d.x=roundtf(d.x); d.y=roundtf(d.y); d.z=roundtf(d.z); d.w=roundtf(d.w);
        out[i] = a; out[i+1] = b; out[i+2] = c; out[i+3] = d;
    }
}

// All four weight matrices in one launch: blockIdx.y selects the source.
__global__ __launch_bounds__(256) void round_w4_k(const float4* __restrict__ w0,
                                                  const float4* __restrict__ w1,
                                                  const float4* __restrict__ w2,
                                                  const float4* __restrict__ w3,
                                                  float4* __restrict__ out, int n4)
{
    const float4* src = (blockIdx.y == 0) ? w0 : (blockIdx.y == 1) ? w1
                      : (blockIdx.y == 2) ? w2 : w3;
    float4* dst = out + (size_t)blockIdx.y * n4;
    int i = (blockIdx.x * blockDim.x + threadIdx.x) * 4;
    if (i + 3 < n4) {
        float4 a = src[i], b = src[i+1], c = src[i+2], d = src[i+3];
        a.x=roundtf(a.x); a.y=roundtf(a.y); a.z=roundtf(a.z); a.w=roundtf(a.w);
        b.x=roundtf(b.x); b.y=roundtf(b.y); b.z=roundtf(b.z); b.w=roundtf(b.w);
        c.x=roundtf(c.x); c.y=roundtf(c.y); c.z=roundtf(c.z); c.w=roundtf(c.w);
        d.x=roundtf(d.x); d.y=roundtf(d.y); d.z=roundtf(d.z); d.w=roundtf(d.w);
        dst[i] = a; dst[i+1] = b; dst[i+2] = c; dst[i+3] = d;
    }
}

// Both caches in one launch: blockIdx.y selects k_cache / v_cache.
__global__ __launch_bounds__(256) void round_c2_k(const float4* __restrict__ c0,
                                                  const float4* __restrict__ c1,
                                                  float4* __restrict__ d0,
                                                  float4* __restrict__ d1, int n4)
{
    const float4* src = (blockIdx.y == 0) ? c0 : c1;
    float4* dst = (blockIdx.y == 0) ? d0 : d1;
    int i = (blockIdx.x * blockDim.x + threadIdx.x) * 4;
    if (i + 3 < n4) {
        float4 a = src[i], b = src[i+1], c = src[i+2], d = src[i+3];
        a.x=roundtf(a.x); a.y=roundtf(a.y); a.z=roundtf(a.z); a.w=roundtf(a.w);
        b.x=roundtf(b.x); b.y=roundtf(b.y); b.z=roundtf(b.z); b.w=roundtf(b.w);
        c.x=roundtf(c.x); c.y=roundtf(c.y); c.z=roundtf(c.z); c.w=roundtf(c.w);
        d.x=roundtf(d.x); d.y=roundtf(d.y); d.z=roundtf(d.z); d.w=roundtf(d.w);
        dst[i] = a; dst[i+1] = b; dst[i+2] = c; dst[i+3] = d;
    }
}

// ================= tf32 mma.sync GEMM (2 CTAs/SM) =================
#define BK       32
#define NCHUNK   (DMODEL / BK)
#define ROWPAD   36
#define TILE_FLOATS (128 * ROWPAD)
#define STAGE_FLOATS (2 * TILE_FLOATS)
#define NSTAGES  3
#define GEMM_SMEM (NSTAGES * STAGE_FLOATS * 4)    // 110592 B; 2x = 216 KB

__device__ __forceinline__ void load_stage(const float* __restrict__ A,
                                           const float* __restrict__ W,
                                           int m0, int n0, int k0,
                                           uint32_t sa, int tid)
{
#pragma unroll
    for (int i = 0; i < 4; ++i) {
        int c = tid + 256 * i;
        int row = c >> 3;
        int j = c & 7;
        cp_async16(sa + (uint32_t)(row * (ROWPAD * 4) + j * 16),
                   A + (size_t)(m0 + row) * DMODEL + k0 + j * 4);
    }
    uint32_t sb = sa + TILE_FLOATS * 4;
#pragma unroll
    for (int i = 0; i < 4; ++i) {
        int c = tid + 256 * i;
        int row = c >> 3;
        int j = c & 7;
        cp_async16(sb + (uint32_t)(row * (ROWPAD * 4) + j * 16),
                   W + (size_t)(n0 + row) * DMODEL + k0 + j * 4);
    }
}

__device__ __forceinline__ void gemm_body(const float* __restrict__ A,
                                          const float* __restrict__ W,
                                          uint32_t smb, int tid, int m0, int n0,
                                          float acc[4][4][4])
{
    int lane = tid & 31;
    int w = tid >> 5;
    int wm = w >> 2;
    int wn = w & 3;
    int lr16 = lane & 15;
    int lc4  = ((lane >> 4) & 1) * 4;
    int br   = (lane & 7) + ((lane >> 4) & 1) * 8;
    int bc4  = ((lane >> 3) & 1) * 4;
    uint32_t a_off[4], b_off[2];
#pragma unroll
    for (int mi = 0; mi < 4; ++mi)
        a_off[mi] = (uint32_t)(((wm * 64 + mi * 16 + lr16) * ROWPAD + lc4) * 4);
#pragma unroll
    for (int njp = 0; njp < 2; ++njp)
        b_off[njp] = (uint32_t)(((wn * 32 + njp * 16 + br) * ROWPAD + bc4) * 4);

    load_stage(A, W, m0, n0, 0, smb, tid);
    CP_COMMIT();
    load_stage(A, W, m0, n0, BK, smb + STAGE_FLOATS * 4, tid);
    CP_COMMIT();

    for (int it = 0; it < NCHUNK; ++it) {
        uint32_t sA = smb + (uint32_t)((it % NSTAGES) * STAGE_FLOATS * 4);
        uint32_t sB = sA + TILE_FLOATS * 4;
        CP_WAIT1();
        __syncthreads();

#pragma unroll
        for (int s = 0; s < 4; ++s) {
            uint32_t koff = (uint32_t)(s * 32);
            uint32_t af[4][4], bq[2][4];
#pragma unroll
            for (int mi = 0; mi < 4; ++mi) ldsm_x4(af[mi], sA + a_off[mi] + koff);
#pragma unroll
            for (int njp = 0; njp < 2; ++njp) ldsm_x4(bq[njp], sB + b_off[njp] + koff);
#pragma unroll
            for (int mi = 0; mi < 4; ++mi)
#pragma unroll
                for (int nj = 0; nj < 4; ++nj)
                    mma_tf32(acc[mi][nj], af[mi], &bq[nj >> 1][(nj & 1) * 2]);
        }

        if (it + 2 < NCHUNK)
            load_stage(A, W, m0, n0, (it + 2) * BK,
                       smb + (uint32_t)(((it + 2) % NSTAGES) * STAGE_FLOATS * 4), tid);
        CP_COMMIT();
    }
}

// Fused QKV projection: blockIdx.z selects proj (0=Q scaled, 1=K, 2=V).
__global__ __launch_bounds__(256, 2) void gemm_qkv(const float* __restrict__ A,
                                                   const float* __restrict__ W0,
                                                   float* __restrict__ Qo,
                                                   float* __restrict__ Ko,
                                                   float* __restrict__ Vo)
{
    extern __shared__ float sm[];
    uint32_t smb = smem_u32(sm);
    int tid = threadIdx.x;
    int pz = blockIdx.z;
    const float* W = W0 + (size_t)pz * DMODEL * DMODEL;
    float* C = (pz == 0) ? Qo : ((pz == 1) ? Ko : Vo);
    float sc = (pz == 0) ? 0.088388347648318447f : 1.0f;
    int m0 = blockIdx.y * 128, n0 = blockIdx.x * 128;

    float acc[4][4][4];
#pragma unroll
    for (int i = 0; i < 4; ++i)
#pragma unroll
        for (int j = 0; j < 4; ++j)
#pragma unroll
            for (int r = 0; r < 4; ++r) acc[i][j][r] = 0.f;

    gemm_body(A, W, smb, tid, m0, n0, acc);

    int lane = tid & 31;
    int w = tid >> 5, wm = w >> 2, wn = w & 3;
    int g = lane >> 2, tg = lane & 3;
#pragma unroll
    for (int mi = 0; mi < 4; ++mi) {
#pragma unroll
        for (int nj = 0; nj < 4; ++nj) {
            int m = m0 + wm * 64 + mi * 16 + g;
            int n = n0 + wn * 32 + nj * 8 + 2 * tg;
            float v0 = roundtf(acc[mi][nj][0] * sc);
            float v1 = roundtf(acc[mi][nj][1] * sc);
            float v2 = roundtf(acc[mi][nj][2] * sc);
            float v3 = roundtf(acc[mi][nj][3] * sc);
            int h_  = n >> 7;
            int hd_ = n & 127;
            {
                int b_ = m >> 11, s_ = m & 2047;
                *reinterpret_cast<float2*>(
                    C + ((((size_t)b_ * NH + h_) * SEQ + s_) * HD + hd_)) = make_float2(v0, v1);
            }
            {
                int m2 = m + 8;
                int b_ = m2 >> 11, s_ = m2 & 2047;
                *reinterpret_cast<float2*>(
                    C + ((((size_t)b_ * NH + h_) * SEQ + s_) * HD + hd_)) = make_float2(v2, v3);
            }
        }
    }
}

// Output projection: plain row-major out.
__global__ __launch_bounds__(256, 2) void gemm_out(const float* __restrict__ A,
                                                   const float* __restrict__ W,
                                                   float* __restrict__ C)
{
    extern __shared__ float sm[];
    uint32_t smb = smem_u32(sm);
    int tid = threadIdx.x;
    int m0 = blockIdx.y * 128, n0 = blockIdx.x * 128;

    float acc[4][4][4];
#pragma unroll
    for (int i = 0; i < 4; ++i)
#pragma unroll
        for (int j = 0; j < 4; ++j)
#pragma unroll
            for (int r = 0; r < 4; ++r) acc[i][j][r] = 0.f;

    gemm_body(A, W, smb, tid, m0, n0, acc);

    int lane = tid & 31;
    int w = tid >> 5, wm = w >> 2, wn = w & 3;
    int g = lane >> 2, tg = lane & 3;
#pragma unroll
    for (int mi = 0; mi < 4; ++mi) {
#pragma unroll
        for (int nj = 0; nj < 4; ++nj) {
            int m = m0 + wm * 64 + mi * 16 + g;
            int n = n0 + wn * 32 + nj * 8 + 2 * tg;
            *reinterpret_cast<float2*>(C + (size_t)m * DMODEL + n) =
                make_float2(acc[mi][nj][0], acc[mi][nj][1]);
            *reinterpret_cast<float2*>(C + (size_t)(m + 8) * DMODEL + n) =
                make_float2(acc[mi][nj][2], acc[mi][nj][3]);
        }
    }
}

// ========== tensor-core flash attention (2 CTAs/SM, KVT=32, 2 syncs/tile) ====
#define KVT   32
#define DPADK 132
#define VPADV 136
#define QPAD  132
#define PPAD  36
#define AT_K    0
#define AT_V    (2 * KVT * DPADK)            // 8448
#define AT_QS   (AT_V + 2 * KVT * VPADV)     // 17152
#define AT_PS   (AT_QS + 64 * QPAD)          // 25600
#define AT_LROW (AT_PS + 64 * PPAD)          // 27904
#define ATTN_SMEM ((AT_LROW + 64) * 4)       // 111872 B

__device__ __forceinline__ void load_kv32(const float* __restrict__ kcb,
                                          const float* __restrict__ vcb,
                                          const float* __restrict__ knb,
                                          const float* __restrict__ vnb,
                                          int t0, int st, uint32_t smb, int tid)
{
    uint32_t sk = smb + (uint32_t)((AT_K + st * KVT * DPADK) * 4);
    uint32_t sv = smb + (uint32_t)((AT_V + st * KVT * VPADV) * 4);
#pragma unroll
    for (int i = 0; i < 4; ++i) {
        int idx = tid + 256 * i;          // 0..1023
        int row = idx >> 5;               // 0..31
        int j = idx & 31;
        int t = t0 + row;
        const float *ks, *vs;
        if (t < CACHEDLEN) { ks = kcb + (size_t)t * HD; vs = vcb + (size_t)t * HD; }
        else               { ks = knb + (size_t)(t - CACHEDLEN) * HD;
                             vs = vnb + (size_t)(t - CACHEDLEN) * HD; }
        cp_async16(sk + (uint32_t)(row * (DPADK * 4) + j * 16), ks + j * 4);
        cp_async16(sv + (uint32_t)(row * (VPADV * 4) + j * 16), vs + j * 4);
    }
}

__global__ __launch_bounds__(256, 2) void attn_tc(
    const float* __restrict__ Q,
    const float* __restrict__ Kn,
    const float* __restrict__ Vn,
    const float* __restrict__ kc,
    const float* __restrict__ vc,
    float* __restrict__ O)
{
    extern __shared__ float sm[];
    uint32_t smb = smem_u32(sm);
    float* Ps   = sm + AT_PS;
    float* lrow = sm + AT_LROW;
    uint32_t qsb = smb + AT_QS * 4;
    uint32_t psb = smb + AT_PS * 4;

    int qt = blockIdx.x, h = blockIdx.y, b = blockIdx.z;
    int tid = threadIdx.x, lane = tid & 31, w = tid >> 5;
    int wm = w >> 1, wn = w & 1;
    int g = lane >> 2, tg = lane & 3;
    int q0 = qt * 64;
    size_t bh = (size_t)b * NH + h;

    if (tid < 64) lrow[tid] = 0.f;

    int lr16 = lane & 15;
    int lc4  = ((lane >> 4) & 1) * 4;
    int br   = (lane & 7) + ((lane >> 4) & 1) * 8;
    int bc4  = ((lane >> 3) & 1) * 4;
    uint32_t a_off = (uint32_t)(((wm * 16 + lr16) * QPAD + lc4) * 4);
    uint32_t k_off = (uint32_t)(((wn * 16 + br) * DPADK + bc4) * 4);
    uint32_t p_off = (uint32_t)(((wm * 16 + lr16) * PPAD + lc4) * 4);

    const float* kcb = kc + bh * CACHEDLEN * HD;
    const float* vcb = vc + bh * CACHEDLEN * HD;
    const float* knb = Kn + bh * SEQ * HD;
    const float* vnb = Vn + bh * SEQ * HD;

    // Q tile + KV tile 0 -> one cp.async group
    const float* Qg = Q + (bh * SEQ + q0) * HD;
#pragma unroll
    for (int i = 0; i < 8; ++i) {
        int idx = tid + 256 * i;
        int row = idx >> 5;
        int j = idx & 31;
        cp_async16(qsb + (uint32_t)(row * (QPAD * 4) + j * 16),
                   Qg + (size_t)row * HD + j * 4);
    }
    load_kv32(kcb, vcb, knb, vnb, 0, 0, smb, tid);
    CP_COMMIT();

    float oa[8][4];
#pragma unroll
    for (int j = 0; j < 8; ++j)
#pragma unroll
        for (int r = 0; r < 4; ++r) oa[j][r] = 0.f;
    float rs0a = 0.f, rs1a = 0.f;     // deferred row-sum accumulators

    int nt = (CACHEDLEN + q0 + 64) / KVT;

    for (int it = 0; it < nt; ++it) {
        CP_WAIT0();                   // tile it data complete
        __syncthreads();              // S1: all warps past PV(it-1), data visible

        // prefetch tile it+1 into the other stage (safe after S1)
        if (it + 1 < nt) {
            load_kv32(kcb, vcb, knb, vnb, (it + 1) * KVT, (it + 1) & 1, smb, tid);
            CP_COMMIT();
        }

        uint32_t sK = smb + (uint32_t)((AT_K + (it & 1) * KVT * DPADK) * 4);
        const float* Vs = sm + AT_V + (it & 1) * KVT * VPADV;

        // ---- S = Q K^T : warp tile 16x16 ----
        float sc[2][4];
#pragma unroll
        for (int nj = 0; nj < 2; ++nj)
#pragma unroll
            for (int r = 0; r < 4; ++r) sc[nj][r] = 0.f;

#pragma unroll
        for (int s = 0; s < 16; ++s) {
            uint32_t koff = (uint32_t)(s * 32);
            uint32_t af[4], kq[4];
            ldsm_x4(af, qsb + a_off + koff);
            ldsm_x4(kq, sK + k_off + koff);
            mma_tf32(sc[0], af, &kq[0]);
            mma_tf32(sc[1], af, &kq[2]);
        }

        // ---- exp + mask + accumulate row sums + store P (tf32-rounded) ----
        int qa0 = CACHEDLEN + q0 + wm * 16 + g;
        int tb  = it * KVT + wn * 16;
#pragma unroll
        for (int nj = 0; nj < 2; ++nj) {
            int c0 = tb + nj * 8 + 2 * tg;
            float p00 = (c0     <= qa0    ) ? roundtf(__expf(sc[nj][0])) : 0.f;
            float p01 = (c0 + 1 <= qa0    ) ? roundtf(__expf(sc[nj][1])) : 0.f;
            float p10 = (c0     <= qa0 + 8) ? roundtf(__expf(sc[nj][2])) : 0.f;
            float p11 = (c0 + 1 <= qa0 + 8) ? roundtf(__expf(sc[nj][3])) : 0.f;
            rs0a += p00 + p01;
            rs1a += p10 + p11;
            int pr = wm * 16 + g;
            int pcol = wn * 16 + nj * 8 + 2 * tg;
            *reinterpret_cast<float2*>(&Ps[pr * PPAD + pcol])       = make_float2(p00, p01);
            *reinterpret_cast<float2*>(&Ps[(pr + 8) * PPAD + pcol]) = make_float2(p10, p11);
        }
        __syncthreads();              // S2: P complete before ldsm reads

        // ---- O += P V : P frags via ldmatrix, V scalar (conflict-free) ----
#pragma unroll
        for (int s = 0; s < 4; ++s) {
            uint32_t pq[4];
            ldsm_x4(pq, psb + p_off + (uint32_t)(s * 32));
            const float* vrow0 = Vs + (8 * s + tg) * VPADV;
            const float* vrow1 = vrow0 + 4 * VPADV;
#pragma unroll
            for (int nj = 0; nj < 8; ++nj) {
                int d0 = wn * 64 + nj * 8 + g;
                uint32_t bf[2];
                bf[0] = __float_as_uint(vrow0[d0]);
                bf[1] = __float_as_uint(vrow1[d0]);
                mma_tf32(oa[nj], pq, bf);
            }
        }
        // no end-of-loop sync: S1 of next iteration provides the ordering
    }

    // final row-sum reduction (once, instead of per tile)
    rs0a += __shfl_xor_sync(0xffffffffu, rs0a, 1);
    rs0a += __shfl_xor_sync(0xffffffffu, rs0a, 2);
    rs1a += __shfl_xor_sync(0xffffffffu, rs1a, 1);
    rs1a += __shfl_xor_sync(0xffffffffu, rs1a, 2);
    if (tg == 0) {
        atomicAdd(&lrow[wm * 16 + g], rs0a);
        atomicAdd(&lrow[wm * 16 + g + 8], rs1a);
    }
    __syncthreads();

    float inv0 = 1.f / lrow[wm * 16 + g];
    float inv1 = 1.f / lrow[wm * 16 + g + 8];
    int row0 = q0 + wm * 16 + g;
#pragma unroll
    for (int nj = 0; nj < 8; ++nj) {
        int d = wn * 64 + nj * 8 + 2 * tg;
        float* dst0 = O + ((size_t)b * SEQ + row0) * DMODEL + h * HD + d;
        float* dst1 = O + ((size_t)b * SEQ + row0 + 8) * DMODEL + h * HD + d;
        *reinterpret_cast<float2*>(dst0) =
            make_float2(roundtf(oa[nj][0] * inv0), roundtf(oa[nj][1] * inv0));
        *reinterpret_cast<float2*>(dst1) =
            make_float2(roundtf(oa[nj][2] * inv1), roundtf(oa[nj][3] * inv1));
    }
}

// ---------------- launch ----------------
extern "C" void kernel_launch(void* const* d_in, const int* in_sizes, int n_in,
                              void* d_out, int out_size)
{
    const float* X  = (const float*)d_in[0];
    const float* Wq = (const float*)d_in[1];
    const float* Wk = (const float*)d_in[2];
    const float* Wv = (const float*)d_in[3];
    const float* Wo = (const float*)d_in[4];
    const float* kc = (const float*)d_in[5];
    const float* vc = (const float*)d_in[6];

    float *Qp, *Kp, *Vp, *Ap, *Xp, *Wp, *Kcp, *Vcp;
    cudaGetSymbolAddress((void**)&Qp,  g_Q);
    cudaGetSymbolAddress((void**)&Kp,  g_Kn);
    cudaGetSymbolAddress((void**)&Vp,  g_Vn);
    cudaGetSymbolAddress((void**)&Ap,  g_At);
    cudaGetSymbolAddress((void**)&Xp,  g_X);
    cudaGetSymbolAddress((void**)&Wp,  g_Wr);
    cudaGetSymbolAddress((void**)&Kcp, g_Kc);
    cudaGetSymbolAddress((void**)&Vcp, g_Vc);

    cudaFuncSetAttribute(gemm_qkv, cudaFuncAttributeMaxDynamicSharedMemorySize, GEMM_SMEM);
    cudaFuncSetAttribute(gemm_out, cudaFuncAttributeMaxDynamicSharedMemorySize, GEMM_SMEM);
    cudaFuncSetAttribute(attn_tc,  cudaFuncAttributeMaxDynamicSharedMemorySize, ATTN_SMEM);

    const int NX = BATCH * SEQ * DMODEL / 4;
    const int NW = DMODEL * DMODEL / 4;
    const int NC = BATCH * NH * CACHEDLEN * HD / 4;

    round_tf32_k<<<NX / 1024, 256>>>((const float4*)X,  (float4*)Xp,  NX);
    round_w4_k<<<dim3(NW / 1024, 4), 256>>>((const float4*)Wq, (const float4*)Wk,
                                            (const float4*)Wv, (const float4*)Wo,
                                            (float4*)Wp, NW);
    round_c2_k<<<dim3(NC / 1024, 2), 256>>>((const float4*)kc, (const float4*)vc,
                                            (float4*)Kcp, (float4*)Vcp, NC);

    dim3 gq(DMODEL / 128, (BATCH * SEQ) / 128, 3);   // fused QKV
    gemm_qkv<<<gq, 256, GEMM_SMEM>>>(Xp, Wp, Qp, Kp, Vp);

    attn_tc<<<dim3(SEQ / 64, NH, BATCH), 256, ATTN_SMEM>>>(Qp, Kp, Vp, Kcp, Vcp, Ap);

    dim3 gg(DMODEL / 128, (BATCH * SEQ) / 128);
    gemm_out<<<gg, 256, GEMM_SMEM>>>(Ap, Wp + 3L * DMODEL * DMODEL, (float*)d_out);
}

// round 13
// speedup vs baseline: 2.2440x; 1.9648x over previous
#include <cuda_runtime.h>
#include <cuda_fp16.h>
#include <cstdint>
#include <math.h>

#define BATCH 2
#define SEQ   2048
#define DMODEL 2048
#define NH    16
#define HD    128
#define CACHEDLEN 2048

// ---------------- scratch (static device globals, fp16) ----------------
__device__ __half g_Qh [(size_t)BATCH*NH*SEQ*HD];   // [B,H,S,HD] pre-scaled
__device__ __half g_Knh[(size_t)BATCH*NH*SEQ*HD];   // [B,H,S,HD]
__device__ __half g_Vnh[(size_t)BATCH*NH*SEQ*HD];   // [B,H,S,HD]
__device__ __half g_Ath[(size_t)BATCH*SEQ*DMODEL];  // [B,S,D]
__device__ __half g_Xh [(size_t)BATCH*SEQ*DMODEL];
__device__ __half g_Wh [(size_t)4*DMODEL*DMODEL];   // Wq,Wk,Wv,Wo
__device__ __half g_Kch[(size_t)BATCH*NH*CACHEDLEN*HD];
__device__ __half g_Vch[(size_t)BATCH*NH*CACHEDLEN*HD];

// ================= helpers =================
__device__ __forceinline__ uint32_t smem_u32(const void* p) {
    uint32_t a;
    asm("{ .reg .u64 t; cvta.to.shared.u64 t, %1; cvt.u32.u64 %0, t; }" : "=r"(a) : "l"(p));
    return a;
}
__device__ __forceinline__ void cp_async16(uint32_t saddr, const void* gptr) {
    asm volatile("cp.async.cg.shared.global [%0], [%1], 16;\n" :: "r"(saddr), "l"(gptr));
}
#define CP_COMMIT() asm volatile("cp.async.commit_group;\n" ::: "memory")
#define CP_WAIT1()  asm volatile("cp.async.wait_group 1;\n" ::: "memory")
#define CP_WAIT0()  asm volatile("cp.async.wait_group 0;\n" ::: "memory")

__device__ __forceinline__ void mma_f16(float c[4], const uint32_t a[4], const uint32_t b[2]) {
    asm volatile(
        "mma.sync.aligned.m16n8k16.row.col.f32.f16.f16.f32 "
        "{%0,%1,%2,%3}, {%4,%5,%6,%7}, {%8,%9}, {%0,%1,%2,%3};"
        : "+f"(c[0]), "+f"(c[1]), "+f"(c[2]), "+f"(c[3])
        : "r"(a[0]), "r"(a[1]), "r"(a[2]), "r"(a[3]), "r"(b[0]), "r"(b[1]));
}
__device__ __forceinline__ void ldsm_x4(uint32_t r[4], uint32_t saddr) {
    asm volatile("ldmatrix.sync.aligned.m8n8.x4.shared.b16 {%0,%1,%2,%3}, [%4];"
                 : "=r"(r[0]), "=r"(r[1]), "=r"(r[2]), "=r"(r[3]) : "r"(saddr));
}
__device__ __forceinline__ void ldsm_x4_t(uint32_t r[4], uint32_t saddr) {
    asm volatile("ldmatrix.sync.aligned.m8n8.x4.trans.shared.b16 {%0,%1,%2,%3}, [%4];"
                 : "=r"(r[0]), "=r"(r[1]), "=r"(r[2]), "=r"(r[3]) : "r"(saddr));
}
__device__ __forceinline__ uint32_t h2u(__half2 h) {
    uint32_t u; *reinterpret_cast<__half2*>(&u) = h; return u;
}

// ================= f32 -> f16 conversion kernels =================
__global__ __launch_bounds__(256) void conv_f2h(const float4* __restrict__ in,
                                                uint4* __restrict__ out, int n8)
{
    int i = blockIdx.x * blockDim.x + threadIdx.x;
    if (i < n8) {
        float4 a = in[2 * i], b = in[2 * i + 1];
        uint4 o;
        o.x = h2u(__floats2half2_rn(a.x, a.y));
        o.y = h2u(__floats2half2_rn(a.z, a.w));
        o.z = h2u(__floats2half2_rn(b.x, b.y));
        o.w = h2u(__floats2half2_rn(b.z, b.w));
        out[i] = o;
    }
}
__global__ __launch_bounds__(256) void conv_w4(const float4* __restrict__ w0,
                                               const float4* __restrict__ w1,
                                               const float4* __restrict__ w2,
                                               const float4* __restrict__ w3,
                                               uint4* __restrict__ out, int n8)
{
    const float4* src = (blockIdx.y == 0) ? w0 : (blockIdx.y == 1) ? w1
                      : (blockIdx.y == 2) ? w2 : w3;
    uint4* dst = out + (size_t)blockIdx.y * n8;
    int i = blockIdx.x * blockDim.x + threadIdx.x;
    if (i < n8) {
        float4 a = src[2 * i], b = src[2 * i + 1];
        uint4 o;
        o.x = h2u(__floats2half2_rn(a.x, a.y));
        o.y = h2u(__floats2half2_rn(a.z, a.w));
        o.z = h2u(__floats2half2_rn(b.x, b.y));
        o.w = h2u(__floats2half2_rn(b.z, b.w));
        dst[i] = o;
    }
}
__global__ __launch_bounds__(256) void conv_c2(const float4* __restrict__ c0,
                                               const float4* __restrict__ c1,
                                               uint4* __restrict__ d0,
                                               uint4* __restrict__ d1, int n8)
{
    const float4* src = (blockIdx.y == 0) ? c0 : c1;
    uint4* dst = (blockIdx.y == 0) ? d0 : d1;
    int i = blockIdx.x * blockDim.x + threadIdx.x;
    if (i < n8) {
        float4 a = src[2 * i], b = src[2 * i + 1];
        uint4 o;
        o.x = h2u(__floats2half2_rn(a.x, a.y));
        o.y = h2u(__floats2half2_rn(a.z, a.w));
        o.z = h2u(__floats2half2_rn(b.x, b.y));
        o.w = h2u(__floats2half2_rn(b.z, b.w));
        dst[i] = o;
    }
}

// ================= fp16 mma.sync GEMM (BK=64, 2 CTAs/SM) =================
#define BKH     64
#define NCHUNKH (DMODEL / BKH)      // 32
#define ROWB    144                  // bytes per smem row (64 halves + 8 pad)
#define TILEB   (128 * ROWB)         // 18432
#define STAGEB  (2 * TILEB)          // 36864
#define GEMM_SMEM (3 * STAGEB)       // 110592; 2x = 216 KB

__device__ __forceinline__ void load_stage_h(const __half* __restrict__ A,
                                             const __half* __restrict__ W,
                                             int m0, int n0, int k0,
                                             uint32_t sa, int tid)
{
#pragma unroll
    for (int i = 0; i < 4; ++i) {
        int c = tid + 256 * i;          // 0..1023
        int row = c >> 3;               // 0..127
        int j = c & 7;                  // 16B chunk (8 halves)
        cp_async16(sa + (uint32_t)(row * ROWB + j * 16),
                   A + (size_t)(m0 + row) * DMODEL + k0 + j * 8);
    }
    uint32_t sb = sa + TILEB;
#pragma unroll
    for (int i = 0; i < 4; ++i) {
        int c = tid + 256 * i;
        int row = c >> 3;
        int j = c & 7;
        cp_async16(sb + (uint32_t)(row * ROWB + j * 16),
                   W + (size_t)(n0 + row) * DMODEL + k0 + j * 8);
    }
}

__device__ __forceinline__ void gemm_body_h(const __half* __restrict__ A,
                                            const __half* __restrict__ W,
                                            uint32_t smb, int tid, int m0, int n0,
                                            float acc[4][4][4])
{
    int lane = tid & 31;
    int w = tid >> 5;
    int wm = w >> 2;                    // 0..1
    int wn = w & 3;                     // 0..3
    int lr16 = lane & 15;
    int hh   = (lane >> 4) & 1;
    uint32_t a_off[4], b_off[2];
#pragma unroll
    for (int mi = 0; mi < 4; ++mi)
        a_off[mi] = (uint32_t)((wm * 64 + mi * 16 + lr16) * ROWB + hh * 16);
#pragma unroll
    for (int p = 0; p < 2; ++p)
        b_off[p] = (uint32_t)((wn * 32 + p * 16 + (lane & 7) + hh * 8) * ROWB
                              + ((lane >> 3) & 1) * 16);

    load_stage_h(A, W, m0, n0, 0, smb, tid);
    CP_COMMIT();
    load_stage_h(A, W, m0, n0, BKH, smb + STAGEB, tid);
    CP_COMMIT();

    for (int it = 0; it < NCHUNKH; ++it) {
        uint32_t sA = smb + (uint32_t)((it % 3) * STAGEB);
        uint32_t sB = sA + TILEB;
        CP_WAIT1();
        __syncthreads();

#pragma unroll
        for (int s = 0; s < 4; ++s) {    // 4 k16 substeps
            uint32_t koff = (uint32_t)(s * 32);
            uint32_t af[4][4], bq[2][4];
#pragma unroll
            for (int mi = 0; mi < 4; ++mi) ldsm_x4(af[mi], sA + a_off[mi] + koff);
#pragma unroll
            for (int p = 0; p < 2; ++p)    ldsm_x4(bq[p], sB + b_off[p] + koff);
#pragma unroll
            for (int mi = 0; mi < 4; ++mi)
#pragma unroll
                for (int nj = 0; nj < 4; ++nj)
                    mma_f16(acc[mi][nj], af[mi], &bq[nj >> 1][(nj & 1) * 2]);
        }

        if (it + 2 < NCHUNKH)
            load_stage_h(A, W, m0, n0, (it + 2) * BKH,
                         smb + (uint32_t)(((it + 2) % 3) * STAGEB), tid);
        CP_COMMIT();
    }
}

// Fused QKV projection -> fp16 scattered [B,H,S,HD]
__global__ __launch_bounds__(256, 2) void gemm_qkv(const __half* __restrict__ A,
                                                   const __half* __restrict__ W0,
                                                   __half* __restrict__ Qo,
                                                   __half* __restrict__ Ko,
                                                   __half* __restrict__ Vo)
{
    extern __shared__ char smc[];
    uint32_t smb = smem_u32(smc);
    int tid = threadIdx.x;
    int pz = blockIdx.z;
    const __half* W = W0 + (size_t)pz * DMODEL * DMODEL;
    __half* C = (pz == 0) ? Qo : ((pz == 1) ? Ko : Vo);
    float sc = (pz == 0) ? 0.088388347648318447f : 1.0f;
    int m0 = blockIdx.y * 128, n0 = blockIdx.x * 128;

    float acc[4][4][4];
#pragma unroll
    for (int i = 0; i < 4; ++i)
#pragma unroll
        for (int j = 0; j < 4; ++j)
#pragma unroll
            for (int r = 0; r < 4; ++r) acc[i][j][r] = 0.f;

    gemm_body_h(A, W, smb, tid, m0, n0, acc);

    int lane = tid & 31;
    int w = tid >> 5, wm = w >> 2, wn = w & 3;
    int g = lane >> 2, tg = lane & 3;
#pragma unroll
    for (int mi = 0; mi < 4; ++mi) {
#pragma unroll
        for (int nj = 0; nj < 4; ++nj) {
            int m = m0 + wm * 64 + mi * 16 + g;
            int n = n0 + wn * 32 + nj * 8 + 2 * tg;
            __half2 lo = __floats2half2_rn(acc[mi][nj][0] * sc, acc[mi][nj][1] * sc);
            __half2 hi = __floats2half2_rn(acc[mi][nj][2] * sc, acc[mi][nj][3] * sc);
            int h_  = n >> 7;
            int hd_ = n & 127;
            {
                int b_ = m >> 11, s_ = m & 2047;
                *reinterpret_cast<__half2*>(
                    C + ((((size_t)b_ * NH + h_) * SEQ + s_) * HD + hd_)) = lo;
            }
            {
                int m2 = m + 8;
                int b_ = m2 >> 11, s_ = m2 & 2047;
                *reinterpret_cast<__half2*>(
                    C + ((((size_t)b_ * NH + h_) * SEQ + s_) * HD + hd_)) = hi;
            }
        }
    }
}

// Output projection: fp16 in, fp32 row-major out.
__global__ __launch_bounds__(256, 2) void gemm_out(const __half* __restrict__ A,
                                                   const __half* __restrict__ W,
                                                   float* __restrict__ C)
{
    extern __shared__ char smc[];
    uint32_t smb = smem_u32(smc);
    int tid = threadIdx.x;
    int m0 = blockIdx.y * 128, n0 = blockIdx.x * 128;

    float acc[4][4][4];
#pragma unroll
    for (int i = 0; i < 4; ++i)
#pragma unroll
        for (int j = 0; j < 4; ++j)
#pragma unroll
            for (int r = 0; r < 4; ++r) acc[i][j][r] = 0.f;

    gemm_body_h(A, W, smb, tid, m0, n0, acc);

    int lane = tid & 31;
    int w = tid >> 5, wm = w >> 2, wn = w & 3;
    int g = lane >> 2, tg = lane & 3;
#pragma unroll
    for (int mi = 0; mi < 4; ++mi) {
#pragma unroll
        for (int nj = 0; nj < 4; ++nj) {
            int m = m0 + wm * 64 + mi * 16 + g;
            int n = n0 + wn * 32 + nj * 8 + 2 * tg;
            *reinterpret_cast<float2*>(C + (size_t)m * DMODEL + n) =
                make_float2(acc[mi][nj][0], acc[mi][nj][1]);
            *reinterpret_cast<float2*>(C + (size_t)(m + 8) * DMODEL + n) =
                make_float2(acc[mi][nj][2], acc[mi][nj][3]);
        }
    }
}

// ========== fp16 tensor-core flash attention (KVT=64, 2 CTAs/SM) ==========
// K/V/Q rows: 128 halves + 8 pad = 136 halves = 272 B (stride ≡ 16 mod 128: ok)
// P rows: 64 halves + 8 pad = 72 halves = 144 B
#define KVT    64
#define KROWB  272
#define PROWB  144
#define AT_K   0                         // 2 stages x 64*272 = 34816
#define AT_V   34816                     // 2 stages x 17408
#define AT_Q   69632                     // 64*272 = 17408
#define AT_P   87040                     // 64*144 = 9216
#define AT_L   96256                     // 64 floats
#define ATTN_SMEM (AT_L + 256)           // 96512 B

__device__ __forceinline__ void load_kv64(const __half* __restrict__ kcb,
                                          const __half* __restrict__ vcb,
                                          const __half* __restrict__ knb,
                                          const __half* __restrict__ vnb,
                                          int t0, int st, uint32_t smb, int tid)
{
    uint32_t sk = smb + (uint32_t)(AT_K + st * 17408);
    uint32_t sv = smb + (uint32_t)(AT_V + st * 17408);
#pragma unroll
    for (int i = 0; i < 4; ++i) {
        int idx = tid + 256 * i;          // 0..1023
        int row = idx >> 4;               // 0..63
        int ch = idx & 15;                // 16B chunk (8 halves)
        int t = t0 + row;
        const __half *ks, *vs;
        if (t < CACHEDLEN) { ks = kcb + (size_t)t * HD; vs = vcb + (size_t)t * HD; }
        else               { ks = knb + (size_t)(t - CACHEDLEN) * HD;
                             vs = vnb + (size_t)(t - CACHEDLEN) * HD; }
        cp_async16(sk + (uint32_t)(row * KROWB + ch * 16), ks + ch * 8);
        cp_async16(sv + (uint32_t)(row * KROWB + ch * 16), vs + ch * 8);
    }
}

__global__ __launch_bounds__(256, 2) void attn_tc(
    const __half* __restrict__ Q,
    const __half* __restrict__ Kn,
    const __half* __restrict__ Vn,
    const __half* __restrict__ kc,
    const __half* __restrict__ vc,
    __half* __restrict__ O)
{
    extern __shared__ char smc[];
    uint32_t smb = smem_u32(smc);
    float* lrow = reinterpret_cast<float*>(smc + AT_L);
    __half* Ps  = reinterpret_cast<__half*>(smc + AT_P);
    uint32_t qsb = smb + AT_Q;
    uint32_t psb = smb + AT_P;

    int qt = blockIdx.x, h = blockIdx.y, b = blockIdx.z;
    int tid = threadIdx.x, lane = tid & 31, w = tid >> 5;
    int wm = w >> 1, wn = w & 1;
    int g = lane >> 2, tg = lane & 3;
    int q0 = qt * 64;
    size_t bh = (size_t)b * NH + h;

    if (tid < 64) lrow[tid] = 0.f;

    int lr16 = lane & 15;
    int hh   = (lane >> 4) & 1;
    uint32_t a_off = (uint32_t)((wm * 16 + lr16) * KROWB + hh * 16);
    uint32_t k_off[2];
#pragma unroll
    for (int p = 0; p < 2; ++p)
        k_off[p] = (uint32_t)((wn * 32 + p * 16 + (lane & 7) + hh * 8) * KROWB
                              + ((lane >> 3) & 1) * 16);
    uint32_t p_off = (uint32_t)((wm * 16 + lr16) * PROWB + hh * 16);
    uint32_t v_off[4];
#pragma unroll
    for (int p = 0; p < 4; ++p)
        v_off[p] = (uint32_t)(lr16 * KROWB + hh * 16 + wn * 128 + p * 32);

    const __half* kcb = kc + bh * CACHEDLEN * HD;
    const __half* vcb = vc + bh * CACHEDLEN * HD;
    const __half* knb = Kn + bh * SEQ * HD;
    const __half* vnb = Vn + bh * SEQ * HD;

    // Q tile + KV tile 0 -> one cp.async group
    const __half* Qg = Q + (bh * SEQ + q0) * HD;
#pragma unroll
    for (int i = 0; i < 4; ++i) {
        int idx = tid + 256 * i;
        int row = idx >> 4;
        int ch = idx & 15;
        cp_async16(qsb + (uint32_t)(row * KROWB + ch * 16),
                   Qg + (size_t)row * HD + ch * 8);
    }
    load_kv64(kcb, vcb, knb, vnb, 0, 0, smb, tid);
    CP_COMMIT();

    float oa[8][4];
#pragma unroll
    for (int j = 0; j < 8; ++j)
#pragma unroll
        for (int r = 0; r < 4; ++r) oa[j][r] = 0.f;
    float rs0a = 0.f, rs1a = 0.f;

    int nt = (CACHEDLEN + q0 + 64) / KVT;

    for (int it = 0; it < nt; ++it) {
        CP_WAIT0();
        __syncthreads();                 // S1

        if (it + 1 < nt) {
            load_kv64(kcb, vcb, knb, vnb, (it + 1) * KVT, (it + 1) & 1, smb, tid);
            CP_COMMIT();
        }

        uint32_t sK = smb + (uint32_t)(AT_K + (it & 1) * 17408);
        uint32_t sV = smb + (uint32_t)(AT_V + (it & 1) * 17408);

        // ---- S = Q K^T : warp tile 16q x 32t, k=128 (8 substeps) ----
        float sc[4][4];
#pragma unroll
        for (int nj = 0; nj < 4; ++nj)
#pragma unroll
            for (int r = 0; r < 4; ++r) sc[nj][r] = 0.f;

#pragma unroll
        for (int s = 0; s < 8; ++s) {
            uint32_t koff = (uint32_t)(s * 32);      // 16 halves
            uint32_t af[4], kq[2][4];
            ldsm_x4(af, qsb + a_off + koff);
            ldsm_x4(kq[0], sK + k_off[0] + koff);
            ldsm_x4(kq[1], sK + k_off[1] + koff);
            mma_f16(sc[0], af, &kq[0][0]);
            mma_f16(sc[1], af, &kq[0][2]);
            mma_f16(sc[2], af, &kq[1][0]);
            mma_f16(sc[3], af, &kq[1][2]);
        }

        // ---- exp (scaled by 2^-4) + mask + row sums + store P fp16 ----
        int qa0 = CACHEDLEN + q0 + wm * 16 + g;
        int tb  = it * KVT + wn * 32;
#pragma unroll
        for (int nj = 0; nj < 4; ++nj) {
            int c0 = tb + nj * 8 + 2 * tg;
            float p00 = (c0     <= qa0    ) ? __expf(sc[nj][0]) * 0.0625f : 0.f;
            float p01 = (c0 + 1 <= qa0    ) ? __expf(sc[nj][1]) * 0.0625f : 0.f;
            float p10 = (c0     <= qa0 + 8) ? __expf(sc[nj][2]) * 0.0625f : 0.f;
            float p11 = (c0 + 1 <= qa0 + 8) ? __expf(sc[nj][3]) * 0.0625f : 0.f;
            rs0a += p00 + p01;
            rs1a += p10 + p11;
            int pr = wm * 16 + g;
            int pcol = wn * 32 + nj * 8 + 2 * tg;
            *reinterpret_cast<__half2*>(Ps + pr * 72 + pcol)       = __floats2half2_rn(p00, p01);
            *reinterpret_cast<__half2*>(Ps + (pr + 8) * 72 + pcol) = __floats2half2_rn(p10, p11);
        }
        __syncthreads();                 // S2: P complete

        // ---- O += P V : warp tile 16q x 64d, k=64t (4 substeps) ----
#pragma unroll
        for (int kc4 = 0; kc4 < 4; ++kc4) {
            uint32_t pq[4];
            ldsm_x4(pq, psb + p_off + (uint32_t)(kc4 * 32));
            uint32_t vbase = sV + (uint32_t)(kc4 * 16 * KROWB);
#pragma unroll
            for (int p = 0; p < 4; ++p) {
                uint32_t vq[4];
                ldsm_x4_t(vq, vbase + v_off[p]);
                mma_f16(oa[2 * p],     pq, &vq[0]);
                mma_f16(oa[2 * p + 1], pq, &vq[2]);
            }
        }
        // no trailing sync: next S1 orders
    }

    rs0a += __shfl_xor_sync(0xffffffffu, rs0a, 1);
    rs0a += __shfl_xor_sync(0xffffffffu, rs0a, 2);
    rs1a += __shfl_xor_sync(0xffffffffu, rs1a, 1);
    rs1a += __shfl_xor_sync(0xffffffffu, rs1a, 2);
    if (tg == 0) {
        atomicAdd(&lrow[wm * 16 + g], rs0a);
        atomicAdd(&lrow[wm * 16 + g + 8], rs1a);
    }
    __syncthreads();

    float inv0 = 1.f / lrow[wm * 16 + g];
    float inv1 = 1.f / lrow[wm * 16 + g + 8];
    int row0 = q0 + wm * 16 + g;
#pragma unroll
    for (int nj = 0; nj < 8; ++nj) {
        int d = wn * 64 + nj * 8 + 2 * tg;
        __half* dst0 = O + ((size_t)b * SEQ + row0) * DMODEL + h * HD + d;
        __half* dst1 = O + ((size_t)b * SEQ + row0 + 8) * DMODEL + h * HD + d;
        *reinterpret_cast<__half2*>(dst0) =
            __floats2half2_rn(oa[nj][0] * inv0, oa[nj][1] * inv0);
        *reinterpret_cast<__half2*>(dst1) =
            __floats2half2_rn(oa[nj][2] * inv1, oa[nj][3] * inv1);
    }
}

// ---------------- launch ----------------
extern "C" void kernel_launch(void* const* d_in, const int* in_sizes, int n_in,
                              void* d_out, int out_size)
{
    const float* X  = (const float*)d_in[0];
    const float* Wq = (const float*)d_in[1];
    const float* Wk = (const float*)d_in[2];
    const float* Wv = (const float*)d_in[3];
    const float* Wo = (const float*)d_in[4];
    const float* kc = (const float*)d_in[5];
    const float* vc = (const float*)d_in[6];

    __half *Qp, *Kp, *Vp, *Ap, *Xp, *Wp, *Kcp, *Vcp;
    cudaGetSymbolAddress((void**)&Qp,  g_Qh);
    cudaGetSymbolAddress((void**)&Kp,  g_Knh);
    cudaGetSymbolAddress((void**)&Vp,  g_Vnh);
    cudaGetSymbolAddress((void**)&Ap,  g_Ath);
    cudaGetSymbolAddress((void**)&Xp,  g_Xh);
    cudaGetSymbolAddress((void**)&Wp,  g_Wh);
    cudaGetSymbolAddress((void**)&Kcp, g_Kch);
    cudaGetSymbolAddress((void**)&Vcp, g_Vch);

    cudaFuncSetAttribute(gemm_qkv, cudaFuncAttributeMaxDynamicSharedMemorySize, GEMM_SMEM);
    cudaFuncSetAttribute(gemm_out, cudaFuncAttributeMaxDynamicSharedMemorySize, GEMM_SMEM);
    cudaFuncSetAttribute(attn_tc,  cudaFuncAttributeMaxDynamicSharedMemorySize, ATTN_SMEM);

    const int NX8 = BATCH * SEQ * DMODEL / 8;          // 1048576
    const int NW8 = DMODEL * DMODEL / 8;               // 524288
    const int NC8 = BATCH * NH * CACHEDLEN * HD / 8;   // 1048576

    conv_f2h<<<NX8 / 256, 256>>>((const float4*)X, (uint4*)Xp, NX8);
    conv_w4<<<dim3(NW8 / 256, 4), 256>>>((const float4*)Wq, (const float4*)Wk,
                                         (const float4*)Wv, (const float4*)Wo,
                                         (uint4*)Wp, NW8);
    conv_c2<<<dim3(NC8 / 256, 2), 256>>>((const float4*)kc, (const float4*)vc,
                                         (uint4*)Kcp, (uint4*)Vcp, NC8);

    dim3 gq(DMODEL / 128, (BATCH * SEQ) / 128, 3);
    gemm_qkv<<<gq, 256, GEMM_SMEM>>>(Xp, Wp, Qp, Kp, Vp);

    attn_tc<<<dim3(SEQ / 64, NH, BATCH), 256, ATTN_SMEM>>>(Qp, Kp, Vp, Kcp, Vcp, Ap);

    dim3 gg(DMODEL / 128, (BATCH * SEQ) / 128);
    gemm_out<<<gg, 256, GEMM_SMEM>>>(Ap, Wp + 3L * DMODEL * DMODEL, (float*)d_out);
}

// round 14
// speedup vs baseline: 2.3861x; 1.0633x over previous
#include <cuda_runtime.h>
#include <cuda_fp16.h>
#include <cstdint>
#include <math.h>

#define BATCH 2
#define SEQ   2048
#define DMODEL 2048
#define NH    16
#define HD    128
#define CACHEDLEN 2048

// ---------------- scratch (static device globals, fp16) ----------------
__device__ __half g_Qh [(size_t)BATCH*NH*SEQ*HD];   // [B,H,S,HD] pre-scaled
__device__ __half g_Knh[(size_t)BATCH*NH*SEQ*HD];
__device__ __half g_Vnh[(size_t)BATCH*NH*SEQ*HD];
__device__ __half g_Ath[(size_t)BATCH*SEQ*DMODEL];
__device__ __half g_Xh [(size_t)BATCH*SEQ*DMODEL];
__device__ __half g_Wh [(size_t)4*DMODEL*DMODEL];
__device__ __half g_Kch[(size_t)BATCH*NH*CACHEDLEN*HD];
__device__ __half g_Vch[(size_t)BATCH*NH*CACHEDLEN*HD];

// ================= helpers =================
__device__ __forceinline__ uint32_t smem_u32(const void* p) {
    uint32_t a;
    asm("{ .reg .u64 t; cvta.to.shared.u64 t, %1; cvt.u32.u64 %0, t; }" : "=r"(a) : "l"(p));
    return a;
}
__device__ __forceinline__ void cp_async16(uint32_t saddr, const void* gptr) {
    asm volatile("cp.async.cg.shared.global [%0], [%1], 16;\n" :: "r"(saddr), "l"(gptr));
}
#define CP_COMMIT() asm volatile("cp.async.commit_group;\n" ::: "memory")
#define CP_WAIT1()  asm volatile("cp.async.wait_group 1;\n" ::: "memory")
#define CP_WAIT0()  asm volatile("cp.async.wait_group 0;\n" ::: "memory")

__device__ __forceinline__ void mma_f16(float c[4], const uint32_t a[4], const uint32_t b[2]) {
    asm volatile(
        "mma.sync.aligned.m16n8k16.row.col.f32.f16.f16.f32 "
        "{%0,%1,%2,%3}, {%4,%5,%6,%7}, {%8,%9}, {%0,%1,%2,%3};"
        : "+f"(c[0]), "+f"(c[1]), "+f"(c[2]), "+f"(c[3])
        : "r"(a[0]), "r"(a[1]), "r"(a[2]), "r"(a[3]), "r"(b[0]), "r"(b[1]));
}
__device__ __forceinline__ void ldsm_x4(uint32_t r[4], uint32_t saddr) {
    asm volatile("ldmatrix.sync.aligned.m8n8.x4.shared.b16 {%0,%1,%2,%3}, [%4];"
                 : "=r"(r[0]), "=r"(r[1]), "=r"(r[2]), "=r"(r[3]) : "r"(saddr));
}
__device__ __forceinline__ void ldsm_x4_t(uint32_t r[4], uint32_t saddr) {
    asm volatile("ldmatrix.sync.aligned.m8n8.x4.trans.shared.b16 {%0,%1,%2,%3}, [%4];"
                 : "=r"(r[0]), "=r"(r[1]), "=r"(r[2]), "=r"(r[3]) : "r"(saddr));
}
__device__ __forceinline__ uint32_t h2u(__half2 h) {
    uint32_t u; *reinterpret_cast<__half2*>(&u) = h; return u;
}

// ================= f32 -> f16 conversion kernels =================
__global__ __launch_bounds__(256) void conv_f2h(const float4* __restrict__ in,
                                                uint4* __restrict__ out, int n8)
{
    int i = blockIdx.x * blockDim.x + threadIdx.x;
    if (i < n8) {
        float4 a = in[2 * i], b = in[2 * i + 1];
        uint4 o;
        o.x = h2u(__floats2half2_rn(a.x, a.y));
        o.y = h2u(__floats2half2_rn(a.z, a.w));
        o.z = h2u(__floats2half2_rn(b.x, b.y));
        o.w = h2u(__floats2half2_rn(b.z, b.w));
        out[i] = o;
    }
}
__global__ __launch_bounds__(256) void conv_w4(const float4* __restrict__ w0,
                                               const float4* __restrict__ w1,
                                               const float4* __restrict__ w2,
                                               const float4* __restrict__ w3,
                                               uint4* __restrict__ out, int n8)
{
    const float4* src = (blockIdx.y == 0) ? w0 : (blockIdx.y == 1) ? w1
                      : (blockIdx.y == 2) ? w2 : w3;
    uint4* dst = out + (size_t)blockIdx.y * n8;
    int i = blockIdx.x * blockDim.x + threadIdx.x;
    if (i < n8) {
        float4 a = src[2 * i], b = src[2 * i + 1];
        uint4 o;
        o.x = h2u(__floats2half2_rn(a.x, a.y));
        o.y = h2u(__floats2half2_rn(a.z, a.w));
        o.z = h2u(__floats2half2_rn(b.x, b.y));
        o.w = h2u(__floats2half2_rn(b.z, b.w));
        dst[i] = o;
    }
}
__global__ __launch_bounds__(256) void conv_c2(const float4* __restrict__ c0,
                                               const float4* __restrict__ c1,
                                               uint4* __restrict__ d0,
                                               uint4* __restrict__ d1, int n8)
{
    const float4* src = (blockIdx.y == 0) ? c0 : c1;
    uint4* dst = (blockIdx.y == 0) ? d0 : d1;
    int i = blockIdx.x * blockDim.x + threadIdx.x;
    if (i < n8) {
        float4 a = src[2 * i], b = src[2 * i + 1];
        uint4 o;
        o.x = h2u(__floats2half2_rn(a.x, a.y));
        o.y = h2u(__floats2half2_rn(a.z, a.w));
        o.z = h2u(__floats2half2_rn(b.x, b.y));
        o.w = h2u(__floats2half2_rn(b.z, b.w));
        dst[i] = o;
    }
}

// ================= fp16 mma.sync GEMM (BK=64, 2 CTAs/SM) — unchanged ========
#define BKH     64
#define NCHUNKH (DMODEL / BKH)
#define ROWB    144
#define TILEB   (128 * ROWB)
#define STAGEB  (2 * TILEB)
#define GEMM_SMEM (3 * STAGEB)

__device__ __forceinline__ void load_stage_h(const __half* __restrict__ A,
                                             const __half* __restrict__ W,
                                             int m0, int n0, int k0,
                                             uint32_t sa, int tid)
{
#pragma unroll
    for (int i = 0; i < 4; ++i) {
        int c = tid + 256 * i;
        int row = c >> 3;
        int j = c & 7;
        cp_async16(sa + (uint32_t)(row * ROWB + j * 16),
                   A + (size_t)(m0 + row) * DMODEL + k0 + j * 8);
    }
    uint32_t sb = sa + TILEB;
#pragma unroll
    for (int i = 0; i < 4; ++i) {
        int c = tid + 256 * i;
        int row = c >> 3;
        int j = c & 7;
        cp_async16(sb + (uint32_t)(row * ROWB + j * 16),
                   W + (size_t)(n0 + row) * DMODEL + k0 + j * 8);
    }
}

__device__ __forceinline__ void gemm_body_h(const __half* __restrict__ A,
                                            const __half* __restrict__ W,
                                            uint32_t smb, int tid, int m0, int n0,
                                            float acc[4][4][4])
{
    int lane = tid & 31;
    int w = tid >> 5;
    int wm = w >> 2;
    int wn = w & 3;
    int lr16 = lane & 15;
    int hh   = (lane >> 4) & 1;
    uint32_t a_off[4], b_off[2];
#pragma unroll
    for (int mi = 0; mi < 4; ++mi)
        a_off[mi] = (uint32_t)((wm * 64 + mi * 16 + lr16) * ROWB + hh * 16);
#pragma unroll
    for (int p = 0; p < 2; ++p)
        b_off[p] = (uint32_t)((wn * 32 + p * 16 + (lane & 7) + hh * 8) * ROWB
                              + ((lane >> 3) & 1) * 16);

    load_stage_h(A, W, m0, n0, 0, smb, tid);
    CP_COMMIT();
    load_stage_h(A, W, m0, n0, BKH, smb + STAGEB, tid);
    CP_COMMIT();

    for (int it = 0; it < NCHUNKH; ++it) {
        uint32_t sA = smb + (uint32_t)((it % 3) * STAGEB);
        uint32_t sB = sA + TILEB;
        CP_WAIT1();
        __syncthreads();

#pragma unroll
        for (int s = 0; s < 4; ++s) {
            uint32_t koff = (uint32_t)(s * 32);
            uint32_t af[4][4], bq[2][4];
#pragma unroll
            for (int mi = 0; mi < 4; ++mi) ldsm_x4(af[mi], sA + a_off[mi] + koff);
#pragma unroll
            for (int p = 0; p < 2; ++p)    ldsm_x4(bq[p], sB + b_off[p] + koff);
#pragma unroll
            for (int mi = 0; mi < 4; ++mi)
#pragma unroll
                for (int nj = 0; nj < 4; ++nj)
                    mma_f16(acc[mi][nj], af[mi], &bq[nj >> 1][(nj & 1) * 2]);
        }

        if (it + 2 < NCHUNKH)
            load_stage_h(A, W, m0, n0, (it + 2) * BKH,
                         smb + (uint32_t)(((it + 2) % 3) * STAGEB), tid);
        CP_COMMIT();
    }
}

__global__ __launch_bounds__(256, 2) void gemm_qkv(const __half* __restrict__ A,
                                                   const __half* __restrict__ W0,
                                                   __half* __restrict__ Qo,
                                                   __half* __restrict__ Ko,
                                                   __half* __restrict__ Vo)
{
    extern __shared__ char smc[];
    uint32_t smb = smem_u32(smc);
    int tid = threadIdx.x;
    int pz = blockIdx.z;
    const __half* W = W0 + (size_t)pz * DMODEL * DMODEL;
    __half* C = (pz == 0) ? Qo : ((pz == 1) ? Ko : Vo);
    float sc = (pz == 0) ? 0.088388347648318447f : 1.0f;
    int m0 = blockIdx.y * 128, n0 = blockIdx.x * 128;

    float acc[4][4][4];
#pragma unroll
    for (int i = 0; i < 4; ++i)
#pragma unroll
        for (int j = 0; j < 4; ++j)
#pragma unroll
            for (int r = 0; r < 4; ++r) acc[i][j][r] = 0.f;

    gemm_body_h(A, W, smb, tid, m0, n0, acc);

    int lane = tid & 31;
    int w = tid >> 5, wm = w >> 2, wn = w & 3;
    int g = lane >> 2, tg = lane & 3;
#pragma unroll
    for (int mi = 0; mi < 4; ++mi) {
#pragma unroll
        for (int nj = 0; nj < 4; ++nj) {
            int m = m0 + wm * 64 + mi * 16 + g;
            int n = n0 + wn * 32 + nj * 8 + 2 * tg;
            __half2 lo = __floats2half2_rn(acc[mi][nj][0] * sc, acc[mi][nj][1] * sc);
            __half2 hi = __floats2half2_rn(acc[mi][nj][2] * sc, acc[mi][nj][3] * sc);
            int h_  = n >> 7;
            int hd_ = n & 127;
            {
                int b_ = m >> 11, s_ = m & 2047;
                *reinterpret_cast<__half2*>(
                    C + ((((size_t)b_ * NH + h_) * SEQ + s_) * HD + hd_)) = lo;
            }
            {
                int m2 = m + 8;
                int b_ = m2 >> 11, s_ = m2 & 2047;
                *reinterpret_cast<__half2*>(
                    C + ((((size_t)b_ * NH + h_) * SEQ + s_) * HD + hd_)) = hi;
            }
        }
    }
}

__global__ __launch_bounds__(256, 2) void gemm_out(const __half* __restrict__ A,
                                                   const __half* __restrict__ W,
                                                   float* __restrict__ C)
{
    extern __shared__ char smc[];
    uint32_t smb = smem_u32(smc);
    int tid = threadIdx.x;
    int m0 = blockIdx.y * 128, n0 = blockIdx.x * 128;

    float acc[4][4][4];
#pragma unroll
    for (int i = 0; i < 4; ++i)
#pragma unroll
        for (int j = 0; j < 4; ++j)
#pragma unroll
            for (int r = 0; r < 4; ++r) acc[i][j][r] = 0.f;

    gemm_body_h(A, W, smb, tid, m0, n0, acc);

    int lane = tid & 31;
    int w = tid >> 5, wm = w >> 2, wn = w & 3;
    int g = lane >> 2, tg = lane & 3;
#pragma unroll
    for (int mi = 0; mi < 4; ++mi) {
#pragma unroll
        for (int nj = 0; nj < 4; ++nj) {
            int m = m0 + wm * 64 + mi * 16 + g;
            int n = n0 + wn * 32 + nj * 8 + 2 * tg;
            *reinterpret_cast<float2*>(C + (size_t)m * DMODEL + n) =
                make_float2(acc[mi][nj][0], acc[mi][nj][1]);
            *reinterpret_cast<float2*>(C + (size_t)(m + 8) * DMODEL + n) =
                make_float2(acc[mi][nj][2], acc[mi][nj][3]);
        }
    }
}

// ========== fp16 attention: Q-tile 128, KVT=32, 2 CTAs/SM ==========
// 8 warps: wm=w>>1 in 0..3 (32 q rows), wn=w&1 (16 t / 64 d).
// K/V/Q rows 272 B (128 halves + 8 pad); P rows 80 B (32 halves + 8 pad).
#define KVT2   32
#define KROWB  272
#define PROWB  80
#define AT_K   0                          // 2 x 32*272 = 17408
#define AT_V   17408                      // 2 x 8704
#define AT_Q   34816                      // 128*272 = 34816
#define AT_P   69632                      // 128*80 = 10240
#define AT_L   79872                      // 128 floats
#define ATTN_SMEM (AT_L + 640)            // 80512 B

__device__ __forceinline__ void load_kv32h(const __half* __restrict__ kcb,
                                           const __half* __restrict__ vcb,
                                           const __half* __restrict__ knb,
                                           const __half* __restrict__ vnb,
                                           int t0, int st, uint32_t smb, int tid)
{
    uint32_t sk = smb + (uint32_t)(AT_K + st * 8704);
    uint32_t sv = smb + (uint32_t)(AT_V + st * 8704);
#pragma unroll
    for (int i = 0; i < 2; ++i) {
        int idx = tid + 256 * i;          // 0..511
        int row = idx >> 4;               // 0..31
        int ch = idx & 15;
        int t = t0 + row;
        const __half *ks, *vs;
        if (t < CACHEDLEN) { ks = kcb + (size_t)t * HD; vs = vcb + (size_t)t * HD; }
        else               { ks = knb + (size_t)(t - CACHEDLEN) * HD;
                             vs = vnb + (size_t)(t - CACHEDLEN) * HD; }
        cp_async16(sk + (uint32_t)(row * KROWB + ch * 16), ks + ch * 8);
        cp_async16(sv + (uint32_t)(row * KROWB + ch * 16), vs + ch * 8);
    }
}

__global__ __launch_bounds__(256, 2) void attn_tc(
    const __half* __restrict__ Q,
    const __half* __restrict__ Kn,
    const __half* __restrict__ Vn,
    const __half* __restrict__ kc,
    const __half* __restrict__ vc,
    __half* __restrict__ O)
{
    extern __shared__ char smc[];
    uint32_t smb = smem_u32(smc);
    float* lrow = reinterpret_cast<float*>(smc + AT_L);
    __half* Ps  = reinterpret_cast<__half*>(smc + AT_P);
    uint32_t qsb = smb + AT_Q;
    uint32_t psb = smb + AT_P;

    int qt = blockIdx.x, h = blockIdx.y, b = blockIdx.z;
    int tid = threadIdx.x, lane = tid & 31, w = tid >> 5;
    int wm = w >> 1, wn = w & 1;
    int g = lane >> 2, tg = lane & 3;
    int q0 = qt * 128;
    size_t bh = (size_t)b * NH + h;

    if (tid < 128) lrow[tid] = 0.f;

    int lr16 = lane & 15;
    int hh   = (lane >> 4) & 1;
    uint32_t a_off[2], p_off[2];
#pragma unroll
    for (int mi = 0; mi < 2; ++mi) {
        a_off[mi] = (uint32_t)((wm * 32 + mi * 16 + lr16) * KROWB + hh * 16);
        p_off[mi] = (uint32_t)((wm * 32 + mi * 16 + lr16) * PROWB + hh * 16);
    }
    uint32_t k_off = (uint32_t)((wn * 16 + (lane & 7) + hh * 8) * KROWB
                                + ((lane >> 3) & 1) * 16);
    uint32_t v_off[4];
#pragma unroll
    for (int p = 0; p < 4; ++p)
        v_off[p] = (uint32_t)(lr16 * KROWB + hh * 16 + wn * 128 + p * 32);

    const __half* kcb = kc + bh * CACHEDLEN * HD;
    const __half* vcb = vc + bh * CACHEDLEN * HD;
    const __half* knb = Kn + bh * SEQ * HD;
    const __half* vnb = Vn + bh * SEQ * HD;

    // Q tile (128 rows) + KV tile 0
    const __half* Qg = Q + (bh * SEQ + q0) * HD;
#pragma unroll
    for (int i = 0; i < 8; ++i) {
        int idx = tid + 256 * i;
        int row = idx >> 4;
        int ch = idx & 15;
        cp_async16(qsb + (uint32_t)(row * KROWB + ch * 16),
                   Qg + (size_t)row * HD + ch * 8);
    }
    load_kv32h(kcb, vcb, knb, vnb, 0, 0, smb, tid);
    CP_COMMIT();

    float oa[2][8][4];
#pragma unroll
    for (int mi = 0; mi < 2; ++mi)
#pragma unroll
        for (int j = 0; j < 8; ++j)
#pragma unroll
            for (int r = 0; r < 4; ++r) oa[mi][j][r] = 0.f;
    float rsa[2][2] = {{0.f, 0.f}, {0.f, 0.f}};

    int nt = (CACHEDLEN + q0 + 128) / KVT2;

    for (int it = 0; it < nt; ++it) {
        CP_WAIT0();
        __syncthreads();                 // S1

        if (it + 1 < nt) {
            load_kv32h(kcb, vcb, knb, vnb, (it + 1) * KVT2, (it + 1) & 1, smb, tid);
            CP_COMMIT();
        }

        uint32_t sK = smb + (uint32_t)(AT_K + (it & 1) * 8704);
        uint32_t sV = smb + (uint32_t)(AT_V + (it & 1) * 8704);

        // ---- S = Q K^T : warp tile 32q x 16t, k=128 ----
        float sc[2][2][4];
#pragma unroll
        for (int mi = 0; mi < 2; ++mi)
#pragma unroll
            for (int nj = 0; nj < 2; ++nj)
#pragma unroll
                for (int r = 0; r < 4; ++r) sc[mi][nj][r] = 0.f;

#pragma unroll
        for (int s = 0; s < 8; ++s) {
            uint32_t koff = (uint32_t)(s * 32);
            uint32_t af[2][4], kq[4];
            ldsm_x4(af[0], qsb + a_off[0] + koff);
            ldsm_x4(af[1], qsb + a_off[1] + koff);
            ldsm_x4(kq, sK + k_off + koff);
#pragma unroll
            for (int mi = 0; mi < 2; ++mi) {
                mma_f16(sc[mi][0], af[mi], &kq[0]);
                mma_f16(sc[mi][1], af[mi], &kq[2]);
            }
        }

        // ---- exp (x 2^-4) + mask + row sums + store P fp16 ----
        int tb = it * KVT2 + wn * 16;
#pragma unroll
        for (int mi = 0; mi < 2; ++mi) {
            int qa0 = CACHEDLEN + q0 + wm * 32 + mi * 16 + g;
            int pr = wm * 32 + mi * 16 + g;
#pragma unroll
            for (int nj = 0; nj < 2; ++nj) {
                int c0 = tb + nj * 8 + 2 * tg;
                float p00 = (c0     <= qa0    ) ? __expf(sc[mi][nj][0]) * 0.0625f : 0.f;
                float p01 = (c0 + 1 <= qa0    ) ? __expf(sc[mi][nj][1]) * 0.0625f : 0.f;
                float p10 = (c0     <= qa0 + 8) ? __expf(sc[mi][nj][2]) * 0.0625f : 0.f;
                float p11 = (c0 + 1 <= qa0 + 8) ? __expf(sc[mi][nj][3]) * 0.0625f : 0.f;
                rsa[mi][0] += p00 + p01;
                rsa[mi][1] += p10 + p11;
                int pcol = wn * 16 + nj * 8 + 2 * tg;
                *reinterpret_cast<__half2*>(Ps + pr * 40 + pcol)       = __floats2half2_rn(p00, p01);
                *reinterpret_cast<__half2*>(Ps + (pr + 8) * 40 + pcol) = __floats2half2_rn(p10, p11);
            }
        }
        __syncthreads();                 // S2

        // ---- O += P V : warp 32q x 64d over k=32t (2 substeps) ----
#pragma unroll
        for (int kc4 = 0; kc4 < 2; ++kc4) {
            uint32_t pq[2][4];
            ldsm_x4(pq[0], psb + p_off[0] + (uint32_t)(kc4 * 32));
            ldsm_x4(pq[1], psb + p_off[1] + (uint32_t)(kc4 * 32));
            uint32_t vbase = sV + (uint32_t)(kc4 * 16 * KROWB);
#pragma unroll
            for (int p = 0; p < 4; ++p) {
                uint32_t vq[4];
                ldsm_x4_t(vq, vbase + v_off[p]);
#pragma unroll
                for (int mi = 0; mi < 2; ++mi) {
                    mma_f16(oa[mi][2 * p],     pq[mi], &vq[0]);
                    mma_f16(oa[mi][2 * p + 1], pq[mi], &vq[2]);
                }
            }
        }
        // no trailing sync: next S1 orders
    }

#pragma unroll
    for (int mi = 0; mi < 2; ++mi) {
        float r0 = rsa[mi][0], r1 = rsa[mi][1];
        r0 += __shfl_xor_sync(0xffffffffu, r0, 1);
        r0 += __shfl_xor_sync(0xffffffffu, r0, 2);
        r1 += __shfl_xor_sync(0xffffffffu, r1, 1);
        r1 += __shfl_xor_sync(0xffffffffu, r1, 2);
        if (tg == 0) {
            atomicAdd(&lrow[wm * 32 + mi * 16 + g], r0);
            atomicAdd(&lrow[wm * 32 + mi * 16 + g + 8], r1);
        }
    }
    __syncthreads();

#pragma unroll
    for (int mi = 0; mi < 2; ++mi) {
        float inv0 = 1.f / lrow[wm * 32 + mi * 16 + g];
        float inv1 = 1.f / lrow[wm * 32 + mi * 16 + g + 8];
        int row0 = q0 + wm * 32 + mi * 16 + g;
#pragma unroll
        for (int nj = 0; nj < 8; ++nj) {
            int d = wn * 64 + nj * 8 + 2 * tg;
            __half* dst0 = O + ((size_t)b * SEQ + row0) * DMODEL + h * HD + d;
            __half* dst1 = O + ((size_t)b * SEQ + row0 + 8) * DMODEL + h * HD + d;
            *reinterpret_cast<__half2*>(dst0) =
                __floats2half2_rn(oa[mi][nj][0] * inv0, oa[mi][nj][1] * inv0);
            *reinterpret_cast<__half2*>(dst1) =
                __floats2half2_rn(oa[mi][nj][2] * inv1, oa[mi][nj][3] * inv1);
        }
    }
}

// ---------------- launch ----------------
extern "C" void kernel_launch(void* const* d_in, const int* in_sizes, int n_in,
                              void* d_out, int out_size)
{
    const float* X  = (const float*)d_in[0];
    const float* Wq = (const float*)d_in[1];
    const float* Wk = (const float*)d_in[2];
    const float* Wv = (const float*)d_in[3];
    const float* Wo = (const float*)d_in[4];
    const float* kc = (const float*)d_in[5];
    const float* vc = (const float*)d_in[6];

    __half *Qp, *Kp, *Vp, *Ap, *Xp, *Wp, *Kcp, *Vcp;
    cudaGetSymbolAddress((void**)&Qp,  g_Qh);
    cudaGetSymbolAddress((void**)&Kp,  g_Knh);
    cudaGetSymbolAddress((void**)&Vp,  g_Vnh);
    cudaGetSymbolAddress((void**)&Ap,  g_Ath);
    cudaGetSymbolAddress((void**)&Xp,  g_Xh);
    cudaGetSymbolAddress((void**)&Wp,  g_Wh);
    cudaGetSymbolAddress((void**)&Kcp, g_Kch);
    cudaGetSymbolAddress((void**)&Vcp, g_Vch);

    cudaFuncSetAttribute(gemm_qkv, cudaFuncAttributeMaxDynamicSharedMemorySize, GEMM_SMEM);
    cudaFuncSetAttribute(gemm_out, cudaFuncAttributeMaxDynamicSharedMemorySize, GEMM_SMEM);
    cudaFuncSetAttribute(attn_tc,  cudaFuncAttributeMaxDynamicSharedMemorySize, ATTN_SMEM);

    const int NX8 = BATCH * SEQ * DMODEL / 8;
    const int NW8 = DMODEL * DMODEL / 8;
    const int NC8 = BATCH * NH * CACHEDLEN * HD / 8;

    conv_f2h<<<NX8 / 256, 256>>>((const float4*)X, (uint4*)Xp, NX8);
    conv_w4<<<dim3(NW8 / 256, 4), 256>>>((const float4*)Wq, (const float4*)Wk,
                                         (const float4*)Wv, (const float4*)Wo,
                                         (uint4*)Wp, NW8);
    conv_c2<<<dim3(NC8 / 256, 2), 256>>>((const float4*)kc, (const float4*)vc,
                                         (uint4*)Kcp, (uint4*)Vcp, NC8);

    dim3 gq(DMODEL / 128, (BATCH * SEQ) / 128, 3);
    gemm_qkv<<<gq, 256, GEMM_SMEM>>>(Xp, Wp, Qp, Kp, Vp);

    attn_tc<<<dim3(SEQ / 128, NH, BATCH), 256, ATTN_SMEM>>>(Qp, Kp, Vp, Kcp, Vcp, Ap);

    dim3 gg(DMODEL / 128, (BATCH * SEQ) / 128);
    gemm_out<<<gg, 256, GEMM_SMEM>>>(Ap, Wp + 3L * DMODEL * DMODEL, (float*)d_out);
}